// round 3
// baseline (speedup 1.0000x reference)
#include <cuda_runtime.h>
#include <cuda_bf16.h>
#include <math.h>
#include <stdint.h>

#define E      1024
#define INNER  2048
#define NHQ    512
#define NH     4
#define DH     512
#define CK     4
#define S      46
#define B      64
#define OUT    512
#define NB     8
#define BS     (B*S)

// ---------------- static scratch (no allocations allowed) ----------------
__device__ float d_x[BS * E];              // residual stream
__device__ float d_up[BS * 2 * INNER];     // [x_in | z]
__device__ float d_xact[BS * INNER];       // silu(conv(x_in))
__device__ float d_gatein[BS * 3 * INNER]; // [q | k | v]
__device__ float d_ipre[B * NH * S];
__device__ float d_fpre[B * NH * S];
__device__ float d_h[BS * INNER];          // raw mlstm out
__device__ float d_last[B * E];            // final LN of last token

// split-bf16 operands
__device__ __nv_bfloat16 d_xlnhi[BS * E];
__device__ __nv_bfloat16 d_xlnlo[BS * E];
__device__ __nv_bfloat16 d_hhi[BS * INNER];
__device__ __nv_bfloat16 d_hlo[BS * INNER];
__device__ __nv_bfloat16 d_wuphi[NB * E * 2 * INNER];
__device__ __nv_bfloat16 d_wuplo[NB * E * 2 * INNER];
__device__ __nv_bfloat16 d_wdnhi[NB * INNER * E];
__device__ __nv_bfloat16 d_wdnlo[NB * INNER * E];

// ---------------- helpers ----------------
__device__ __forceinline__ uint32_t smem_u32(const void* p) {
    return (uint32_t)__cvta_generic_to_shared(p);
}
__device__ __forceinline__ void ldsm4(uint32_t& r0, uint32_t& r1, uint32_t& r2, uint32_t& r3, uint32_t addr) {
    asm volatile("ldmatrix.sync.aligned.m8n8.x4.shared.b16 {%0,%1,%2,%3}, [%4];"
                 : "=r"(r0), "=r"(r1), "=r"(r2), "=r"(r3) : "r"(addr));
}
__device__ __forceinline__ void ldsm4t(uint32_t& r0, uint32_t& r1, uint32_t& r2, uint32_t& r3, uint32_t addr) {
    asm volatile("ldmatrix.sync.aligned.m8n8.x4.trans.shared.b16 {%0,%1,%2,%3}, [%4];"
                 : "=r"(r0), "=r"(r1), "=r"(r2), "=r"(r3) : "r"(addr));
}
__device__ __forceinline__ void mma16816(float* d, const uint32_t* a, const uint32_t* b) {
    asm volatile("mma.sync.aligned.m16n8k16.row.col.f32.bf16.bf16.f32 "
                 "{%0,%1,%2,%3}, {%4,%5,%6,%7}, {%8,%9}, {%0,%1,%2,%3};"
                 : "+f"(d[0]), "+f"(d[1]), "+f"(d[2]), "+f"(d[3])
                 : "r"(a[0]), "r"(a[1]), "r"(a[2]), "r"(a[3]), "r"(b[0]), "r"(b[1]));
}
__device__ __forceinline__ void split1(float x, __nv_bfloat16& h, __nv_bfloat16& l) {
    h = __float2bfloat16_rn(x);
    l = __float2bfloat16_rn(x - __bfloat162float(h));
}

// ---------------- fp32 -> (hi,lo) bf16 split ----------------
__global__ __launch_bounds__(256) void split_kernel(
    const float* __restrict__ src, __nv_bfloat16* __restrict__ hi,
    __nv_bfloat16* __restrict__ lo, size_t n)
{
    size_t i = ((size_t)blockIdx.x * 256 + threadIdx.x) * 4;
    if (i >= n) return;
    float4 v = *(const float4*)(src + i);
    __nv_bfloat16 h0, h1, h2, h3, l0, l1, l2, l3;
    split1(v.x, h0, l0); split1(v.y, h1, l1);
    split1(v.z, h2, l2); split1(v.w, h3, l3);
    *(__nv_bfloat162*)(hi + i)     = __nv_bfloat162(h0, h1);
    *(__nv_bfloat162*)(hi + i + 2) = __nv_bfloat162(h2, h3);
    *(__nv_bfloat162*)(lo + i)     = __nv_bfloat162(l0, l1);
    *(__nv_bfloat162*)(lo + i + 2) = __nv_bfloat162(l2, l3);
}

// ---------------- LayerNorm (rows of E), optional split output ----------------
template<int SPLIT>
__global__ __launch_bounds__(256) void ln_kernel(
    const float* __restrict__ in, size_t in_stride,
    const float* __restrict__ w,
    float* __restrict__ outf,
    __nv_bfloat16* __restrict__ oh, __nv_bfloat16* __restrict__ ol,
    size_t out_stride)
{
    int row = blockIdx.x;
    const float* x = in + (size_t)row * in_stride;
    int tid = threadIdx.x;
    float s = 0.f, ss = 0.f;
    for (int i = tid; i < E; i += 256) { float v = x[i]; s += v; ss += v * v; }
    __shared__ float r1[256], r2[256];
    r1[tid] = s; r2[tid] = ss;
    __syncthreads();
    for (int st = 128; st > 0; st >>= 1) {
        if (tid < st) { r1[tid] += r1[tid + st]; r2[tid] += r2[tid + st]; }
        __syncthreads();
    }
    float mean = r1[0] * (1.f / E);
    float var  = r2[0] * (1.f / E) - mean * mean;
    float inv  = rsqrtf(var + 1e-5f);
    for (int i = tid; i < E; i += 256) {
        float v = (x[i] - mean) * inv * w[i];
        if (SPLIT) {
            __nv_bfloat16 h, l;
            split1(v, h, l);
            oh[(size_t)row * out_stride + i] = h;
            ol[(size_t)row * out_stride + i] = l;
        } else {
            outf[(size_t)row * out_stride + i] = v;
        }
    }
}

// ---------------- split-bf16 128x128x32 GEMM (3-term), optional C += ----------------
template<int ADD>
__global__ __launch_bounds__(256) void gemm_kernel(
    const __nv_bfloat16* __restrict__ Ahg, const __nv_bfloat16* __restrict__ Alg,
    const __nv_bfloat16* __restrict__ Bhg, const __nv_bfloat16* __restrict__ Blg,
    float* __restrict__ C, int M, int N, int Kd)
{
    __shared__ __nv_bfloat16 sAh[128][40], sAl[128][40];
    __shared__ __nv_bfloat16 sBh[32][136], sBl[32][136];

    int tid  = threadIdx.x;
    int lane = tid & 31, warp = tid >> 5;
    int bm = blockIdx.y * 128, bn = blockIdx.x * 128;
    int wm = (warp >> 1) * 32;
    int wn = (warp & 1) * 64;

    int ar0 = tid >> 2,          ac0 = (tid & 3) * 8;
    int ar1 = (tid + 256) >> 2,  ac1 = (tid & 3) * 8;
    int br0 = tid >> 4,          bc0 = (tid & 15) * 8;
    int br1 = (tid + 256) >> 4,  bc1 = (tid & 15) * 8;

    size_t aoff0 = (size_t)(bm + ar0) * Kd + ac0;
    size_t aoff1 = (size_t)(bm + ar1) * Kd + ac1;
    size_t boff0 = (size_t)br0 * N + bn + bc0;
    size_t boff1 = (size_t)br1 * N + bn + bc1;

    int a_row = lane & 15, a_col = (lane >> 4) * 8;
    int b_row = (lane & 7) + ((lane >> 3) & 1) * 8;
    int b_col = (lane >> 4) * 8;

    float acc[2][8][4];
    #pragma unroll
    for (int i = 0; i < 2; i++)
        #pragma unroll
        for (int j = 0; j < 8; j++)
            #pragma unroll
            for (int q = 0; q < 4; q++) acc[i][j][q] = 0.f;

    int ntiles = Kd >> 5;
    uint4 pAh0 = *(const uint4*)(Ahg + aoff0);
    uint4 pAh1 = *(const uint4*)(Ahg + aoff1);
    uint4 pAl0 = *(const uint4*)(Alg + aoff0);
    uint4 pAl1 = *(const uint4*)(Alg + aoff1);
    uint4 pBh0 = *(const uint4*)(Bhg + boff0);
    uint4 pBh1 = *(const uint4*)(Bhg + boff1);
    uint4 pBl0 = *(const uint4*)(Blg + boff0);
    uint4 pBl1 = *(const uint4*)(Blg + boff1);

    for (int kt = 0; kt < ntiles; kt++) {
        *(uint4*)&sAh[ar0][ac0] = pAh0;
        *(uint4*)&sAh[ar1][ac1] = pAh1;
        *(uint4*)&sAl[ar0][ac0] = pAl0;
        *(uint4*)&sAl[ar1][ac1] = pAl1;
        *(uint4*)&sBh[br0][bc0] = pBh0;
        *(uint4*)&sBh[br1][bc1] = pBh1;
        *(uint4*)&sBl[br0][bc0] = pBl0;
        *(uint4*)&sBl[br1][bc1] = pBl1;
        __syncthreads();

        if (kt + 1 < ntiles) {
            int k0 = (kt + 1) * 32;
            pAh0 = *(const uint4*)(Ahg + aoff0 + k0);
            pAh1 = *(const uint4*)(Ahg + aoff1 + k0);
            pAl0 = *(const uint4*)(Alg + aoff0 + k0);
            pAl1 = *(const uint4*)(Alg + aoff1 + k0);
            pBh0 = *(const uint4*)(Bhg + boff0 + (size_t)k0 * N);
            pBh1 = *(const uint4*)(Bhg + boff1 + (size_t)k0 * N);
            pBl0 = *(const uint4*)(Blg + boff0 + (size_t)k0 * N);
            pBl1 = *(const uint4*)(Blg + boff1 + (size_t)k0 * N);
        }

        #pragma unroll
        for (int h = 0; h < 2; h++) {
            uint32_t ah[2][4], al[2][4];
            #pragma unroll
            for (int mt = 0; mt < 2; mt++) {
                ldsm4(ah[mt][0], ah[mt][1], ah[mt][2], ah[mt][3],
                      smem_u32(&sAh[wm + mt * 16 + a_row][h * 16 + a_col]));
                ldsm4(al[mt][0], al[mt][1], al[mt][2], al[mt][3],
                      smem_u32(&sAl[wm + mt * 16 + a_row][h * 16 + a_col]));
            }
            #pragma unroll
            for (int ng = 0; ng < 4; ng++) {
                uint32_t bh[4], bl[4];
                ldsm4t(bh[0], bh[1], bh[2], bh[3],
                       smem_u32(&sBh[h * 16 + b_row][wn + ng * 16 + b_col]));
                ldsm4t(bl[0], bl[1], bl[2], bl[3],
                       smem_u32(&sBl[h * 16 + b_row][wn + ng * 16 + b_col]));
                #pragma unroll
                for (int mt = 0; mt < 2; mt++) {
                    #pragma unroll
                    for (int nn = 0; nn < 2; nn++) {
                        float* d = acc[mt][ng * 2 + nn];
                        mma16816(d, ah[mt], &bh[nn * 2]);
                        mma16816(d, ah[mt], &bl[nn * 2]);
                        mma16816(d, al[mt], &bh[nn * 2]);
                    }
                }
            }
        }
        __syncthreads();
    }

    int g = lane >> 2, t2 = (lane & 3) * 2;
    #pragma unroll
    for (int mt = 0; mt < 2; mt++) {
        #pragma unroll
        for (int nt = 0; nt < 8; nt++) {
            int row = bm + wm + mt * 16 + g;
            int col = bn + wn + nt * 8 + t2;
            float* d = acc[mt][nt];
            float2* p0 = (float2*)&C[(size_t)row * N + col];
            float2* p1 = (float2*)&C[(size_t)(row + 8) * N + col];
            float2 v0 = make_float2(d[0], d[1]);
            float2 v1 = make_float2(d[2], d[3]);
            if (ADD) {
                float2 o0 = *p0, o1 = *p1;
                v0.x += o0.x; v0.y += o0.y;
                v1.x += o1.x; v1.y += o1.y;
            }
            *p0 = v0; *p1 = v1;
        }
    }
}

// ---------------- fused causal dwconv + SiLU + headwise q/k/v ----------------
// thread = one hq head (4 channels); walks s; all weights in registers
__global__ __launch_bounds__(128) void conv_head_kernel(
    const float* __restrict__ cw, const float* __restrict__ cb,
    const float* __restrict__ wq, const float* __restrict__ wk,
    const float* __restrict__ wv)
{
    int hq = blockIdx.x * 128 + threadIdx.x;   // 0..511
    int b  = blockIdx.y;
    float Wq[16], Wk[16], Wv[16], Cw[16];
    #pragma unroll
    for (int i = 0; i < 4; i++) {
        ((float4*)Wq)[i] = ((const float4*)(wq + hq * 16))[i];
        ((float4*)Wk)[i] = ((const float4*)(wk + hq * 16))[i];
        ((float4*)Wv)[i] = ((const float4*)(wv + hq * 16))[i];
        ((float4*)Cw)[i] = ((const float4*)(cw + hq * 16))[i];
    }
    float4 bias4 = *(const float4*)(cb + hq * 4);
    float bias[4] = {bias4.x, bias4.y, bias4.z, bias4.w};
    float h0[4] = {0,0,0,0}, h1[4] = {0,0,0,0}, h2[4] = {0,0,0,0};

    for (int s = 0; s < S; s++) {
        size_t row = (size_t)b * S + s;
        float xi[4], a[4];
        *(float4*)xi = *(const float4*)(d_up + row * 2 * INNER + hq * 4);
        #pragma unroll
        for (int j = 0; j < 4; j++) {
            float o = Cw[j*4+0]*h0[j] + Cw[j*4+1]*h1[j] + Cw[j*4+2]*h2[j]
                    + Cw[j*4+3]*xi[j] + bias[j];
            a[j] = o / (1.f + expf(-o));
            h0[j] = h1[j]; h1[j] = h2[j]; h2[j] = xi[j];
        }
        *(float4*)(d_xact + row * INNER + hq * 4) = *(float4*)a;
        float qo[4], ko[4], vo[4];
        #pragma unroll
        for (int o = 0; o < 4; o++) {
            float sq = 0.f, sk = 0.f, sv = 0.f;
            #pragma unroll
            for (int d = 0; d < 4; d++) {
                sq += Wq[o*4+d] * a[d];
                sk += Wk[o*4+d] * a[d];
                sv += Wv[o*4+d] * xi[d];
            }
            qo[o] = sq; ko[o] = sk; vo[o] = sv;
        }
        float* gp = d_gatein + row * 3 * INNER;
        *(float4*)(gp + hq * 4)             = *(float4*)qo;
        *(float4*)(gp + INNER + hq * 4)     = *(float4*)ko;
        *(float4*)(gp + 2 * INNER + hq * 4) = *(float4*)vo;
    }
}

// ---------------- gate pre-activations: 16 rows per block, smem weights ----------------
__global__ __launch_bounds__(256) void gate_kernel(
    const float* __restrict__ igw, const float* __restrict__ igb,
    const float* __restrict__ fgw, const float* __restrict__ fgb)
{
    __shared__ float sw[512][8];
    int tid = threadIdx.x;
    int r = tid >> 4, l = tid & 15;
    int row = blockIdx.x * 16 + r;
    int b = row / S, s = row - b * S;
    const float* g = d_gatein + (size_t)row * 3 * INNER;
    float acc[8] = {0,0,0,0,0,0,0,0};

    for (int k0 = 0; k0 < 3 * INNER; k0 += 512) {
        for (int i = tid; i < 512; i += 256) {
            float4 a = *(const float4*)(igw + (size_t)(k0 + i) * NH);
            float4 f = *(const float4*)(fgw + (size_t)(k0 + i) * NH);
            *(float4*)&sw[i][0] = a;
            *(float4*)&sw[i][4] = f;
        }
        __syncthreads();
        #pragma unroll 4
        for (int kk = l; kk < 512; kk += 16) {
            float gv = g[k0 + kk];
            float4 w0 = *(float4*)&sw[kk][0];
            float4 w1 = *(float4*)&sw[kk][4];
            acc[0] += gv * w0.x; acc[1] += gv * w0.y;
            acc[2] += gv * w0.z; acc[3] += gv * w0.w;
            acc[4] += gv * w1.x; acc[5] += gv * w1.y;
            acc[6] += gv * w1.z; acc[7] += gv * w1.w;
        }
        __syncthreads();
    }
    #pragma unroll
    for (int off = 8; off; off >>= 1)
        #pragma unroll
        for (int j = 0; j < 8; j++)
            acc[j] += __shfl_down_sync(0xffffffffu, acc[j], off, 16);
    if (l == 0) {
        #pragma unroll
        for (int j = 0; j < 4; j++) {
            d_ipre[(b * NH + j) * S + s] = acc[j] + igb[j];
            d_fpre[(b * NH + j) * S + s] = acc[j + 4] + fgb[j];
        }
    }
}

// ---------------- mLSTM: one block per (b, h); k/v read once ----------------
__global__ __launch_bounds__(256) void mlstm2_kernel()
{
    int bh = blockIdx.x;          // 0..B*NH-1
    int b = bh >> 2, hh = bh & 3;
    int tid = threadIdx.x;
    int warp = tid >> 5, lane = tid & 31;

    __shared__ float sq[46][65];
    __shared__ float sk[48][65];     // rows 46,47 zero-padded; reused for v
    __shared__ float ssc[48][48];    // raw scores -> normalized coeffs
    __shared__ float scum[48], sip[48];

    const float* gbase = d_gatein + (size_t)b * S * 3 * INNER + (size_t)hh * DH;

    // in-block cumsum of log-sigmoid(fpre) + load ipre
    if (tid == 0) {
        float acc = 0.f;
        const float* f = d_fpre + (size_t)bh * S;
        for (int s = 0; s < S; s++) {
            float x = f[s];
            float ls = (x < 0.f) ? (x - log1pf(expf(x))) : (-log1pf(expf(-x)));
            acc += ls;
            scum[s] = acc;
        }
    }
    if (tid < S) sip[tid] = d_ipre[bh * S + tid];

    // ---------- phase 1: raw scores q@k^T over 8 chunks of 64 dims ----------
    float acc1[2][2][4];
    #pragma unroll
    for (int p = 0; p < 2; p++)
        #pragma unroll
        for (int i = 0; i < 2; i++)
            #pragma unroll
            for (int j = 0; j < 4; j++) acc1[p][i][j] = 0.f;

    for (int ch = 0; ch < 8; ch++) {
        for (int idx = tid; idx < S * 64; idx += 256) {
            int r = idx >> 6, c = idx & 63;
            sq[r][c] = gbase[(size_t)r * 3 * INNER + ch * 64 + c];
            sk[r][c] = gbase[(size_t)r * 3 * INNER + INNER + ch * 64 + c];
        }
        if (tid < 128) sk[46 + (tid >> 6)][tid & 63] = 0.f;
        __syncthreads();
        #pragma unroll
        for (int p = 0; p < 2; p++) {
            int tile = p * 256 + tid;
            if (tile < 276) {
                int tt = tile / 12, ss = tile % 12;
                int t0 = tt * 2, s0 = ss * 4;
                #pragma unroll 8
                for (int d = 0; d < 64; d++) {
                    float q0 = sq[t0][d], q1 = sq[t0 + 1][d];
                    float k0 = sk[s0][d], k1 = sk[s0 + 1][d];
                    float k2 = sk[s0 + 2][d], k3 = sk[s0 + 3][d];
                    acc1[p][0][0] += q0 * k0; acc1[p][0][1] += q0 * k1;
                    acc1[p][0][2] += q0 * k2; acc1[p][0][3] += q0 * k3;
                    acc1[p][1][0] += q1 * k0; acc1[p][1][1] += q1 * k1;
                    acc1[p][1][2] += q1 * k2; acc1[p][1][3] += q1 * k3;
                }
            }
        }
        __syncthreads();
    }
    #pragma unroll
    for (int p = 0; p < 2; p++) {
        int tile = p * 256 + tid;
        if (tile < 276) {
            int tt = tile / 12, ss = tile % 12;
            #pragma unroll
            for (int i = 0; i < 2; i++)
                #pragma unroll
                for (int j = 0; j < 4; j++)
                    ssc[tt * 2 + i][ss * 4 + j] = acc1[p][i][j];
        }
    }
    // zero pad rows 46,47 (read by phase 3 when t0=44)
    if (tid < 96) ssc[46 + tid / 48][tid % 48] = 0.f;
    __syncthreads();

    // ---------- phase 2: stabilized normalization, warp per t ----------
    const float scale = 0.04419417382f;   // 512^-0.5
    for (int t = warp; t < S; t += 8) {
        float ct = scum[t];
        int s1 = lane, s2 = lane + 32;
        float ld1 = (s1 <= t) ? (ct - scum[s1] + sip[s1]) : -INFINITY;
        float ld2 = (s2 <= t && s2 < S) ? (ct - scum[s2] + sip[s2]) : -INFINITY;
        float m = fmaxf(ld1, ld2);
        #pragma unroll
        for (int off = 16; off; off >>= 1)
            m = fmaxf(m, __shfl_xor_sync(0xffffffffu, m, off));
        float cv1 = (s1 <= t) ? ssc[t][s1] * scale * expf(ld1 - m) : 0.f;
        float cv2 = (s2 <= t && s2 < S) ? ssc[t][s2] * scale * expf(ld2 - m) : 0.f;
        float cs = cv1 + cv2;
        #pragma unroll
        for (int off = 16; off; off >>= 1)
            cs += __shfl_xor_sync(0xffffffffu, cs, off);
        float denom = fmaxf(fabsf(cs), expf(-m)) + 1e-6f;
        float inv = 1.f / denom;
        ssc[t][s1] = cv1 * inv;
        if (s2 < 48) ssc[t][s2] = cv2 * inv;
    }
    __syncthreads();

    // ---------- phase 3: h = coeff @ v over 8 chunks of 64 dims ----------
    int tt3 = tid >> 4, cc = tid & 15;   // 16 t-tiles? no: 12 used
    for (int ch = 0; ch < 8; ch++) {
        for (int idx = tid; idx < S * 64; idx += 256) {
            int r = idx >> 6, c = idx & 63;
            sk[r][c] = gbase[(size_t)r * 3 * INNER + 2 * INNER + ch * 64 + c];
        }
        __syncthreads();
        if (tt3 < 12) {
            int t0 = tt3 * 4, c0 = cc * 4;
            float hacc[4][4];
            #pragma unroll
            for (int i = 0; i < 4; i++)
                #pragma unroll
                for (int j = 0; j < 4; j++) hacc[i][j] = 0.f;
            for (int s = 0; s < S; s++) {
                float c0v = ssc[t0][s], c1v = ssc[t0+1][s];
                float c2v = ssc[t0+2][s], c3v = ssc[t0+3][s];
                float v0 = sk[s][c0], v1 = sk[s][c0+1];
                float v2 = sk[s][c0+2], v3 = sk[s][c0+3];
                hacc[0][0] += c0v*v0; hacc[0][1] += c0v*v1; hacc[0][2] += c0v*v2; hacc[0][3] += c0v*v3;
                hacc[1][0] += c1v*v0; hacc[1][1] += c1v*v1; hacc[1][2] += c1v*v2; hacc[1][3] += c1v*v3;
                hacc[2][0] += c2v*v0; hacc[2][1] += c2v*v1; hacc[2][2] += c2v*v2; hacc[2][3] += c2v*v3;
                hacc[3][0] += c3v*v0; hacc[3][1] += c3v*v1; hacc[3][2] += c3v*v2; hacc[3][3] += c3v*v3;
            }
            #pragma unroll
            for (int i = 0; i < 4; i++) {
                int t = t0 + i;
                if (t < S)
                    *(float4*)(d_h + (size_t)(b * S + t) * INNER + hh * DH + ch * 64 + c0)
                        = *(float4*)hacc[i];
            }
        }
        __syncthreads();
    }
}

// ---------------- per-head norm + skip + z-gating -> split bf16 h ----------------
__global__ __launch_bounds__(256) void mhnorm_kernel(
    const float* __restrict__ mhw, const float* __restrict__ skipw)
{
    int row = blockIdx.x;
    int hh  = blockIdx.y;
    int tid = threadIdx.x;
    const float* hp = d_h + (size_t)row * INNER + (size_t)hh * DH;
    float v0 = hp[tid], v1 = hp[tid + 256];
    __shared__ float r1[256], r2[256];
    r1[tid] = v0 + v1;
    r2[tid] = v0 * v0 + v1 * v1;
    __syncthreads();
    for (int st = 128; st > 0; st >>= 1) {
        if (tid < st) { r1[tid] += r1[tid + st]; r2[tid] += r2[tid + st]; }
        __syncthreads();
    }
    float mean = r1[0] * (1.f / DH);
    float var  = r2[0] * (1.f / DH) - mean * mean;
    float inv  = rsqrtf(var + 1e-5f);
    #pragma unroll
    for (int p = 0; p < 2; p++) {
        int i = tid + p * 256;
        int c = hh * DH + i;
        float z  = d_up[(size_t)row * 2 * INNER + INNER + c];
        float sz = z / (1.f + expf(-z));
        float hv = p ? v1 : v0;
        float val = ((hv - mean) * inv * mhw[c] + skipw[c] * d_xact[(size_t)row * INNER + c]) * sz;
        __nv_bfloat16 hi, lo;
        split1(val, hi, lo);
        d_hhi[(size_t)row * INNER + c] = hi;
        d_hlo[(size_t)row * INNER + c] = lo;
    }
}

// ---------------- final projection ----------------
__global__ void proj_kernel(const float* __restrict__ pw,
                            const float* __restrict__ pb,
                            float* __restrict__ out)
{
    int o = blockIdx.x * blockDim.x + threadIdx.x;
    int b = blockIdx.y;
    const float* l = d_last + (size_t)b * E;
    float acc = pb[o];
    for (int e = 0; e < E; e++) acc += l[e] * pw[(size_t)e * OUT + o];
    out[b * OUT + o] = acc;
}

// ---------------- host launcher ----------------
extern "C" void kernel_launch(void* const* d_in, const int* in_sizes, int n_in,
                              void* d_out, int out_size)
{
    const float* in_x      = (const float*)d_in[0];
    const float* ln_w      = (const float*)d_in[1];
    const float* w_up      = (const float*)d_in[2];
    const float* conv_w    = (const float*)d_in[3];
    const float* conv_b    = (const float*)d_in[4];
    const float* wq        = (const float*)d_in[5];
    const float* wk        = (const float*)d_in[6];
    const float* wv        = (const float*)d_in[7];
    const float* ig_w      = (const float*)d_in[8];
    const float* ig_b      = (const float*)d_in[9];
    const float* fg_w      = (const float*)d_in[10];
    const float* fg_b      = (const float*)d_in[11];
    const float* skip      = (const float*)d_in[12];
    const float* mhn_w     = (const float*)d_in[13];
    const float* w_down    = (const float*)d_in[14];
    const float* post_ln_w = (const float*)d_in[15];
    const float* proj_w    = (const float*)d_in[16];
    const float* proj_b    = (const float*)d_in[17];
    float* out = (float*)d_out;

    float *px, *plast;
    __nv_bfloat16 *pxh, *pxl, *phh, *phl, *puh, *pul, *pdh, *pdl;
    cudaGetSymbolAddress((void**)&px,    d_x);
    cudaGetSymbolAddress((void**)&plast, d_last);
    cudaGetSymbolAddress((void**)&pxh,   d_xlnhi);
    cudaGetSymbolAddress((void**)&pxl,   d_xlnlo);
    cudaGetSymbolAddress((void**)&phh,   d_hhi);
    cudaGetSymbolAddress((void**)&phl,   d_hlo);
    cudaGetSymbolAddress((void**)&puh,   d_wuphi);
    cudaGetSymbolAddress((void**)&pul,   d_wuplo);
    cudaGetSymbolAddress((void**)&pdh,   d_wdnhi);
    cudaGetSymbolAddress((void**)&pdl,   d_wdnlo);

    float* pup;
    cudaGetSymbolAddress((void**)&pup, d_up);

    cudaMemcpyAsync(px, in_x, sizeof(float) * (size_t)BS * E,
                    cudaMemcpyDeviceToDevice);

    {
        size_t nu = (size_t)NB * E * 2 * INNER;
        split_kernel<<<(unsigned)(nu / 4 / 256), 256>>>(w_up, puh, pul, nu);
        size_t nd = (size_t)NB * INNER * E;
        split_kernel<<<(unsigned)(nd / 4 / 256), 256>>>(w_down, pdh, pdl, nd);
    }

    for (int bi = 0; bi < NB; bi++) {
        ln_kernel<1><<<BS, 256>>>(px, E, ln_w + (size_t)bi * E,
                                  nullptr, pxh, pxl, E);

        dim3 gu(2 * INNER / 128, BS / 128);
        gemm_kernel<0><<<gu, 256>>>(pxh, pxl,
                                    puh + (size_t)bi * E * 2 * INNER,
                                    pul + (size_t)bi * E * 2 * INNER,
                                    pup, BS, 2 * INNER, E);

        conv_head_kernel<<<dim3(NHQ / 128, B), 128>>>(
            conv_w + (size_t)bi * INNER * CK, conv_b + (size_t)bi * INNER,
            wq + (size_t)bi * NHQ * 16, wk + (size_t)bi * NHQ * 16,
            wv + (size_t)bi * NHQ * 16);

        gate_kernel<<<BS / 16, 256>>>(
            ig_w + (size_t)bi * 3 * INNER * NH, ig_b + (size_t)bi * NH,
            fg_w + (size_t)bi * 3 * INNER * NH, fg_b + (size_t)bi * NH);

        mlstm2_kernel<<<B * NH, 256>>>();

        mhnorm_kernel<<<dim3(BS, NH), 256>>>(
            mhn_w + (size_t)bi * INNER, skip + (size_t)bi * INNER);

        dim3 gd(E / 128, BS / 128);
        gemm_kernel<1><<<gd, 256>>>(phh, phl,
                                    pdh + (size_t)bi * INNER * E,
                                    pdl + (size_t)bi * INNER * E,
                                    px, BS, E, INNER);
    }

    ln_kernel<0><<<B, 256>>>(px + (size_t)(S - 1) * E, (size_t)S * E,
                             post_ln_w, plast, nullptr, nullptr, E);
    proj_kernel<<<dim3(OUT / 256, B), 256>>>(proj_w, proj_b, out);
}

// round 4
// speedup vs baseline: 1.1184x; 1.1184x over previous
#include <cuda_runtime.h>
#include <cuda_bf16.h>
#include <math.h>
#include <stdint.h>

#define E      1024
#define INNER  2048
#define NHQ    512
#define NH     4
#define DH     512
#define CK     4
#define S      46
#define B      64
#define OUT    512
#define NB     8
#define BS     (B*S)

// ---------------- static scratch (no allocations allowed) ----------------
__device__ float d_x[BS * E];
__device__ float d_up[BS * 2 * INNER];
__device__ float d_xact[BS * INNER];
__device__ float d_gatein[BS * 3 * INNER];
__device__ float d_ipre[B * NH * S];
__device__ float d_fpre[B * NH * S];
__device__ float d_cum[B * NH * S];
__device__ float d_h[BS * INNER];
__device__ float d_last[B * E];

__device__ __nv_bfloat16 d_xlnhi[BS * E];
__device__ __nv_bfloat16 d_xlnlo[BS * E];
__device__ __nv_bfloat16 d_hhi[BS * INNER];
__device__ __nv_bfloat16 d_hlo[BS * INNER];
__device__ __nv_bfloat16 d_wuphi[NB * E * 2 * INNER];
__device__ __nv_bfloat16 d_wuplo[NB * E * 2 * INNER];
__device__ __nv_bfloat16 d_wdnhi[NB * INNER * E];
__device__ __nv_bfloat16 d_wdnlo[NB * INNER * E];

// ---------------- helpers ----------------
__device__ __forceinline__ uint32_t smem_u32(const void* p) {
    return (uint32_t)__cvta_generic_to_shared(p);
}
__device__ __forceinline__ void ldsm4(uint32_t& r0, uint32_t& r1, uint32_t& r2, uint32_t& r3, uint32_t addr) {
    asm volatile("ldmatrix.sync.aligned.m8n8.x4.shared.b16 {%0,%1,%2,%3}, [%4];"
                 : "=r"(r0), "=r"(r1), "=r"(r2), "=r"(r3) : "r"(addr));
}
__device__ __forceinline__ void ldsm4t(uint32_t& r0, uint32_t& r1, uint32_t& r2, uint32_t& r3, uint32_t addr) {
    asm volatile("ldmatrix.sync.aligned.m8n8.x4.trans.shared.b16 {%0,%1,%2,%3}, [%4];"
                 : "=r"(r0), "=r"(r1), "=r"(r2), "=r"(r3) : "r"(addr));
}
__device__ __forceinline__ void mma16816(float* d, const uint32_t* a, const uint32_t* b) {
    asm volatile("mma.sync.aligned.m16n8k16.row.col.f32.bf16.bf16.f32 "
                 "{%0,%1,%2,%3}, {%4,%5,%6,%7}, {%8,%9}, {%0,%1,%2,%3};"
                 : "+f"(d[0]), "+f"(d[1]), "+f"(d[2]), "+f"(d[3])
                 : "r"(a[0]), "r"(a[1]), "r"(a[2]), "r"(a[3]), "r"(b[0]), "r"(b[1]));
}
__device__ __forceinline__ void cpa16(void* sdst, const void* gsrc) {
    asm volatile("cp.async.cg.shared.global [%0], [%1], 16;"
                 :: "r"(smem_u32(sdst)), "l"(gsrc));
}
__device__ __forceinline__ void split1(float x, __nv_bfloat16& h, __nv_bfloat16& l) {
    h = __float2bfloat16_rn(x);
    l = __float2bfloat16_rn(x - __bfloat162float(h));
}

// ---------------- fp32 -> (hi,lo) bf16 split ----------------
__global__ __launch_bounds__(256) void split_kernel(
    const float* __restrict__ src, __nv_bfloat16* __restrict__ hi,
    __nv_bfloat16* __restrict__ lo, size_t n)
{
    size_t i = ((size_t)blockIdx.x * 256 + threadIdx.x) * 4;
    if (i >= n) return;
    float4 v = *(const float4*)(src + i);
    __nv_bfloat16 h0, h1, h2, h3, l0, l1, l2, l3;
    split1(v.x, h0, l0); split1(v.y, h1, l1);
    split1(v.z, h2, l2); split1(v.w, h3, l3);
    *(__nv_bfloat162*)(hi + i)     = __nv_bfloat162(h0, h1);
    *(__nv_bfloat162*)(hi + i + 2) = __nv_bfloat162(h2, h3);
    *(__nv_bfloat162*)(lo + i)     = __nv_bfloat162(l0, l1);
    *(__nv_bfloat162*)(lo + i + 2) = __nv_bfloat162(l2, l3);
}

// ---------------- LayerNorm ----------------
template<int SPLIT>
__global__ __launch_bounds__(256) void ln_kernel(
    const float* __restrict__ in, size_t in_stride,
    const float* __restrict__ w,
    float* __restrict__ outf,
    __nv_bfloat16* __restrict__ oh, __nv_bfloat16* __restrict__ ol,
    size_t out_stride)
{
    int row = blockIdx.x;
    const float* x = in + (size_t)row * in_stride;
    int tid = threadIdx.x;
    float s = 0.f, ss = 0.f;
    for (int i = tid; i < E; i += 256) { float v = x[i]; s += v; ss += v * v; }
    __shared__ float r1[256], r2[256];
    r1[tid] = s; r2[tid] = ss;
    __syncthreads();
    for (int st = 128; st > 0; st >>= 1) {
        if (tid < st) { r1[tid] += r1[tid + st]; r2[tid] += r2[tid + st]; }
        __syncthreads();
    }
    float mean = r1[0] * (1.f / E);
    float var  = r2[0] * (1.f / E) - mean * mean;
    float inv  = rsqrtf(var + 1e-5f);
    for (int i = tid; i < E; i += 256) {
        float v = (x[i] - mean) * inv * w[i];
        if (SPLIT) {
            __nv_bfloat16 h, l;
            split1(v, h, l);
            oh[(size_t)row * out_stride + i] = h;
            ol[(size_t)row * out_stride + i] = l;
        } else {
            outf[(size_t)row * out_stride + i] = v;
        }
    }
}

// ---------------- split-bf16 GEMM, cp.async 2-stage pipeline ----------------
// smem layout (dynamic):
//   ah: 2 stages x 128x40 bf16   al: same
//   bh: 2 stages x 32x136 bf16   bl: same
#define A_STAGE 5120   // 128*40 elems
#define B_STAGE 4352   // 32*136 elems
#define GEMM_SMEM_BYTES ((2*A_STAGE*2 + 2*B_STAGE*2) * 2)

template<int ADD>
__global__ __launch_bounds__(256, 2) void gemm_kernel(
    const __nv_bfloat16* __restrict__ Ahg, const __nv_bfloat16* __restrict__ Alg,
    const __nv_bfloat16* __restrict__ Bhg, const __nv_bfloat16* __restrict__ Blg,
    float* __restrict__ C, int M, int N, int Kd)
{
    extern __shared__ __nv_bfloat16 smem[];
    __nv_bfloat16* ah = smem;
    __nv_bfloat16* al = ah + 2 * A_STAGE;
    __nv_bfloat16* bh = al + 2 * A_STAGE;
    __nv_bfloat16* bl = bh + 2 * B_STAGE;

    int tid  = threadIdx.x;
    int lane = tid & 31, warp = tid >> 5;
    int bm = blockIdx.y * 128, bn = blockIdx.x * 128;
    int wm = (warp >> 1) * 32;
    int wn = (warp & 1) * 64;

    int ar0 = tid >> 2,          ac0 = (tid & 3) * 8;
    int ar1 = (tid + 256) >> 2,  ac1 = (tid & 3) * 8;
    int br0 = tid >> 4,          bc0 = (tid & 15) * 8;
    int br1 = (tid + 256) >> 4,  bc1 = (tid & 15) * 8;

    size_t aoff0 = (size_t)(bm + ar0) * Kd + ac0;
    size_t aoff1 = (size_t)(bm + ar1) * Kd + ac1;
    size_t boff0 = (size_t)br0 * N + bn + bc0;
    size_t boff1 = (size_t)br1 * N + bn + bc1;

    int a_row = lane & 15, a_col = (lane >> 4) * 8;
    int b_row = (lane & 7) + ((lane >> 3) & 1) * 8;
    int b_col = (lane >> 4) * 8;

    float acc[2][8][4];
    #pragma unroll
    for (int i = 0; i < 2; i++)
        #pragma unroll
        for (int j = 0; j < 8; j++)
            #pragma unroll
            for (int q = 0; q < 4; q++) acc[i][j][q] = 0.f;

    int ntiles = Kd >> 5;

    // stage issue helper (8 x cp.async 16B per thread)
    auto issue = [&](int st, int kt) {
        int k0 = kt * 32;
        __nv_bfloat16* A0 = ah + st * A_STAGE;
        __nv_bfloat16* A1 = al + st * A_STAGE;
        __nv_bfloat16* B0 = bh + st * B_STAGE;
        __nv_bfloat16* B1 = bl + st * B_STAGE;
        cpa16(A0 + ar0 * 40 + ac0, Ahg + aoff0 + k0);
        cpa16(A0 + ar1 * 40 + ac1, Ahg + aoff1 + k0);
        cpa16(A1 + ar0 * 40 + ac0, Alg + aoff0 + k0);
        cpa16(A1 + ar1 * 40 + ac1, Alg + aoff1 + k0);
        cpa16(B0 + br0 * 136 + bc0, Bhg + boff0 + (size_t)k0 * N);
        cpa16(B0 + br1 * 136 + bc1, Bhg + boff1 + (size_t)k0 * N);
        cpa16(B1 + br0 * 136 + bc0, Blg + boff0 + (size_t)k0 * N);
        cpa16(B1 + br1 * 136 + bc1, Blg + boff1 + (size_t)k0 * N);
        asm volatile("cp.async.commit_group;");
    };

    issue(0, 0);

    for (int kt = 0; kt < ntiles; kt++) {
        int st = kt & 1;
        if (kt + 1 < ntiles) {
            issue(st ^ 1, kt + 1);
            asm volatile("cp.async.wait_group 1;");
        } else {
            asm volatile("cp.async.wait_group 0;");
        }
        __syncthreads();

        __nv_bfloat16* A0 = ah + st * A_STAGE;
        __nv_bfloat16* A1 = al + st * A_STAGE;
        __nv_bfloat16* B0 = bh + st * B_STAGE;
        __nv_bfloat16* B1 = bl + st * B_STAGE;

        #pragma unroll
        for (int h = 0; h < 2; h++) {
            uint32_t rah[2][4], ral[2][4];
            #pragma unroll
            for (int mt = 0; mt < 2; mt++) {
                ldsm4(rah[mt][0], rah[mt][1], rah[mt][2], rah[mt][3],
                      smem_u32(A0 + (wm + mt * 16 + a_row) * 40 + h * 16 + a_col));
                ldsm4(ral[mt][0], ral[mt][1], ral[mt][2], ral[mt][3],
                      smem_u32(A1 + (wm + mt * 16 + a_row) * 40 + h * 16 + a_col));
            }
            #pragma unroll
            for (int ng = 0; ng < 4; ng++) {
                uint32_t rbh[4], rbl[4];
                ldsm4t(rbh[0], rbh[1], rbh[2], rbh[3],
                       smem_u32(B0 + (h * 16 + b_row) * 136 + wn + ng * 16 + b_col));
                ldsm4t(rbl[0], rbl[1], rbl[2], rbl[3],
                       smem_u32(B1 + (h * 16 + b_row) * 136 + wn + ng * 16 + b_col));
                #pragma unroll
                for (int mt = 0; mt < 2; mt++) {
                    #pragma unroll
                    for (int nn = 0; nn < 2; nn++) {
                        float* d = acc[mt][ng * 2 + nn];
                        mma16816(d, rah[mt], &rbh[nn * 2]);
                        mma16816(d, rah[mt], &rbl[nn * 2]);
                        mma16816(d, ral[mt], &rbh[nn * 2]);
                    }
                }
            }
        }
        __syncthreads();
    }

    int g = lane >> 2, t2 = (lane & 3) * 2;
    #pragma unroll
    for (int mt = 0; mt < 2; mt++) {
        #pragma unroll
        for (int nt = 0; nt < 8; nt++) {
            int row = bm + wm + mt * 16 + g;
            int col = bn + wn + nt * 8 + t2;
            float* d = acc[mt][nt];
            float2* p0 = (float2*)&C[(size_t)row * N + col];
            float2* p1 = (float2*)&C[(size_t)(row + 8) * N + col];
            float2 v0 = make_float2(d[0], d[1]);
            float2 v1 = make_float2(d[2], d[3]);
            if (ADD) {
                float2 o0 = *p0, o1 = *p1;
                v0.x += o0.x; v0.y += o0.y;
                v1.x += o1.x; v1.y += o1.y;
            }
            *p0 = v0; *p1 = v1;
        }
    }
}

// ---------------- causal depthwise conv (K=4) + SiLU (round-2 version) ----------------
__global__ __launch_bounds__(256) void conv_silu_kernel(
    const float* __restrict__ cw, const float* __restrict__ cb)
{
    int c = blockIdx.x * 256 + threadIdx.x;
    int b = blockIdx.y;
    float w0 = cw[c * CK + 0], w1 = cw[c * CK + 1];
    float w2 = cw[c * CK + 2], w3 = cw[c * CK + 3];
    float bias = cb[c];
    const float* src = d_up + (size_t)b * S * 2 * INNER + c;
    float* dst = d_xact + (size_t)b * S * INNER + c;
    float x0 = 0.f, x1 = 0.f, x2 = 0.f;
    for (int s = 0; s < S; s++) {
        float x3 = src[(size_t)s * 2 * INNER];
        float o = w0 * x0 + w1 * x1 + w2 * x2 + w3 * x3 + bias;
        dst[(size_t)s * INNER] = o / (1.f + expf(-o));
        x0 = x1; x1 = x2; x2 = x3;
    }
}

// ---------------- headwise 4x4 q/k/v (round-2 version) ----------------
__global__ __launch_bounds__(128) void headwise_kernel(
    const float* __restrict__ wq, const float* __restrict__ wk,
    const float* __restrict__ wv)
{
    int hq = blockIdx.x * 128 + threadIdx.x;
    int r0 = blockIdx.y * 16;
    float Wq[16], Wk[16], Wv[16];
    #pragma unroll
    for (int i = 0; i < 4; i++) {
        ((float4*)Wq)[i] = ((const float4*)(wq + hq * 16))[i];
        ((float4*)Wk)[i] = ((const float4*)(wk + hq * 16))[i];
        ((float4*)Wv)[i] = ((const float4*)(wv + hq * 16))[i];
    }
    #pragma unroll 4
    for (int r = 0; r < 16; r++) {
        int row = r0 + r;
        float a[4], xi[4];
        *(float4*)a  = *(const float4*)(d_xact + (size_t)row * INNER + hq * 4);
        *(float4*)xi = *(const float4*)(d_up + (size_t)row * 2 * INNER + hq * 4);
        float qo[4], ko[4], vo[4];
        #pragma unroll
        for (int o = 0; o < 4; o++) {
            float sq = 0.f, sk = 0.f, sv = 0.f;
            #pragma unroll
            for (int d = 0; d < 4; d++) {
                sq += Wq[o * 4 + d] * a[d];
                sk += Wk[o * 4 + d] * a[d];
                sv += Wv[o * 4 + d] * xi[d];
            }
            qo[o] = sq; ko[o] = sk; vo[o] = sv;
        }
        float* gp = d_gatein + (size_t)row * 3 * INNER;
        *(float4*)(gp + hq * 4)             = *(float4*)qo;
        *(float4*)(gp + INNER + hq * 4)     = *(float4*)ko;
        *(float4*)(gp + 2 * INNER + hq * 4) = *(float4*)vo;
    }
}

// ---------------- gate pre-activations (round-2 version) ----------------
__global__ __launch_bounds__(256) void gate_kernel(
    const float* __restrict__ igw, const float* __restrict__ igb,
    const float* __restrict__ fgw, const float* __restrict__ fgb)
{
    int row = blockIdx.x;
    int b = row / S, s = row - b * S;
    int tid = threadIdx.x;
    const float* g = d_gatein + (size_t)row * 3 * INNER;
    float acc[8] = {0.f,0.f,0.f,0.f,0.f,0.f,0.f,0.f};
    for (int r = tid; r < 3 * INNER; r += 256) {
        float gv = g[r];
        float4 iw = *(const float4*)(igw + (size_t)r * NH);
        float4 fw = *(const float4*)(fgw + (size_t)r * NH);
        acc[0] += gv * iw.x; acc[1] += gv * iw.y;
        acc[2] += gv * iw.z; acc[3] += gv * iw.w;
        acc[4] += gv * fw.x; acc[5] += gv * fw.y;
        acc[6] += gv * fw.z; acc[7] += gv * fw.w;
    }
    __shared__ float red[8][256];
    #pragma unroll
    for (int h = 0; h < 8; h++) red[h][tid] = acc[h];
    __syncthreads();
    for (int st = 128; st > 0; st >>= 1) {
        if (tid < st) {
            #pragma unroll
            for (int h = 0; h < 8; h++) red[h][tid] += red[h][tid + st];
        }
        __syncthreads();
    }
    if (tid < 4)
        d_ipre[(b * NH + tid) * S + s] = red[tid][0] + igb[tid];
    else if (tid < 8)
        d_fpre[(b * NH + (tid - 4)) * S + s] = red[tid][0] + fgb[tid - 4];
}

// ---------------- cumsum of log-sigmoid(fpre) ----------------
__global__ void cumsum_kernel()
{
    int i = blockIdx.x * blockDim.x + threadIdx.x;
    if (i >= B * NH) return;
    const float* f = d_fpre + (size_t)i * S;
    float* c = d_cum + (size_t)i * S;
    float acc = 0.f;
    for (int s = 0; s < S; s++) {
        float x = f[s];
        float ls = (x < 0.f) ? (x - log1pf(expf(x))) : (-log1pf(expf(-x)));
        acc += ls;
        c[s] = acc;
    }
}

// ---------------- mLSTM: one block per (b, h, t) (round-2 version) ----------------
__global__ __launch_bounds__(256) void mlstm_kernel()
{
    int t  = blockIdx.x;
    int bh = blockIdx.y;
    int b = bh / NH, hh = bh - b * NH;
    int tid = threadIdx.x;
    int warp = tid >> 5, lane = tid & 31;

    __shared__ float qs[DH];
    __shared__ float cums[S], ips[S];
    __shared__ float coeff[S];

    const float* gbase = d_gatein + (size_t)b * S * 3 * INNER;
    const float* qrow = gbase + (size_t)t * 3 * INNER + hh * DH;
    for (int i = tid; i < DH; i += 256) qs[i] = qrow[i];
    if (tid < S) { cums[tid] = d_cum[bh * S + tid]; ips[tid] = d_ipre[bh * S + tid]; }
    __syncthreads();

    int nvalid = t + 1;
    for (int s = warp; s < nvalid; s += 8) {
        const float* krow = gbase + (size_t)s * 3 * INNER + INNER + hh * DH;
        float p = 0.f;
        for (int j = lane; j < DH; j += 32) p += qs[j] * krow[j];
        #pragma unroll
        for (int off = 16; off; off >>= 1) p += __shfl_down_sync(0xffffffffu, p, off);
        if (lane == 0) coeff[s] = p;
    }
    __syncthreads();

    if (tid == 0) {
        float ct = cums[t];
        float m = -INFINITY;
        for (int s = 0; s < nvalid; s++) {
            float ld = ct - cums[s] + ips[s];
            if (ld > m) m = ld;
        }
        const float scale = rsqrtf((float)DH);
        float csum = 0.f;
        for (int s = 0; s < nvalid; s++) {
            float ld = ct - cums[s] + ips[s];
            float cv = coeff[s] * scale * expf(ld - m);
            coeff[s] = cv;
            csum += cv;
        }
        float denom = fmaxf(fabsf(csum), expf(-m)) + 1e-6f;
        float inv = 1.f / denom;
        for (int s = 0; s < nvalid; s++) coeff[s] *= inv;
    }
    __syncthreads();

    float acc0 = 0.f, acc1 = 0.f;
    int d0 = tid, d1 = tid + 256;
    for (int s = 0; s < nvalid; s++) {
        const float* vrow = gbase + (size_t)s * 3 * INNER + 2 * INNER + hh * DH;
        float cs = coeff[s];
        acc0 += cs * vrow[d0];
        acc1 += cs * vrow[d1];
    }
    float* hrow = d_h + (size_t)(b * S + t) * INNER + hh * DH;
    hrow[d0] = acc0;
    hrow[d1] = acc1;
}

// ---------------- per-head norm + skip + z-gating -> split bf16 h ----------------
__global__ __launch_bounds__(256) void mhnorm_kernel(
    const float* __restrict__ mhw, const float* __restrict__ skipw)
{
    int row = blockIdx.x;
    int hh  = blockIdx.y;
    int tid = threadIdx.x;
    const float* hp = d_h + (size_t)row * INNER + (size_t)hh * DH;
    float v0 = hp[tid], v1 = hp[tid + 256];
    __shared__ float r1[256], r2[256];
    r1[tid] = v0 + v1;
    r2[tid] = v0 * v0 + v1 * v1;
    __syncthreads();
    for (int st = 128; st > 0; st >>= 1) {
        if (tid < st) { r1[tid] += r1[tid + st]; r2[tid] += r2[tid + st]; }
        __syncthreads();
    }
    float mean = r1[0] * (1.f / DH);
    float var  = r2[0] * (1.f / DH) - mean * mean;
    float inv  = rsqrtf(var + 1e-5f);
    #pragma unroll
    for (int p = 0; p < 2; p++) {
        int i = tid + p * 256;
        int c = hh * DH + i;
        float z  = d_up[(size_t)row * 2 * INNER + INNER + c];
        float sz = z / (1.f + expf(-z));
        float hv = p ? v1 : v0;
        float val = ((hv - mean) * inv * mhw[c] + skipw[c] * d_xact[(size_t)row * INNER + c]) * sz;
        __nv_bfloat16 hi, lo;
        split1(val, hi, lo);
        d_hhi[(size_t)row * INNER + c] = hi;
        d_hlo[(size_t)row * INNER + c] = lo;
    }
}

// ---------------- final projection ----------------
__global__ void proj_kernel(const float* __restrict__ pw,
                            const float* __restrict__ pb,
                            float* __restrict__ out)
{
    int o = blockIdx.x * blockDim.x + threadIdx.x;
    int b = blockIdx.y;
    const float* l = d_last + (size_t)b * E;
    float acc = pb[o];
    for (int e = 0; e < E; e++) acc += l[e] * pw[(size_t)e * OUT + o];
    out[b * OUT + o] = acc;
}

// ---------------- host launcher ----------------
extern "C" void kernel_launch(void* const* d_in, const int* in_sizes, int n_in,
                              void* d_out, int out_size)
{
    const float* in_x      = (const float*)d_in[0];
    const float* ln_w      = (const float*)d_in[1];
    const float* w_up      = (const float*)d_in[2];
    const float* conv_w    = (const float*)d_in[3];
    const float* conv_b    = (const float*)d_in[4];
    const float* wq        = (const float*)d_in[5];
    const float* wk        = (const float*)d_in[6];
    const float* wv        = (const float*)d_in[7];
    const float* ig_w      = (const float*)d_in[8];
    const float* ig_b      = (const float*)d_in[9];
    const float* fg_w      = (const float*)d_in[10];
    const float* fg_b      = (const float*)d_in[11];
    const float* skip      = (const float*)d_in[12];
    const float* mhn_w     = (const float*)d_in[13];
    const float* w_down    = (const float*)d_in[14];
    const float* post_ln_w = (const float*)d_in[15];
    const float* proj_w    = (const float*)d_in[16];
    const float* proj_b    = (const float*)d_in[17];
    float* out = (float*)d_out;

    float *px, *pup, *plast;
    __nv_bfloat16 *pxh, *pxl, *phh, *phl, *puh, *pul, *pdh, *pdl;
    cudaGetSymbolAddress((void**)&px,    d_x);
    cudaGetSymbolAddress((void**)&pup,   d_up);
    cudaGetSymbolAddress((void**)&plast, d_last);
    cudaGetSymbolAddress((void**)&pxh,   d_xlnhi);
    cudaGetSymbolAddress((void**)&pxl,   d_xlnlo);
    cudaGetSymbolAddress((void**)&phh,   d_hhi);
    cudaGetSymbolAddress((void**)&phl,   d_hlo);
    cudaGetSymbolAddress((void**)&puh,   d_wuphi);
    cudaGetSymbolAddress((void**)&pul,   d_wuplo);
    cudaGetSymbolAddress((void**)&pdh,   d_wdnhi);
    cudaGetSymbolAddress((void**)&pdl,   d_wdnlo);

    static bool attr_set = false;
    if (!attr_set) {
        cudaFuncSetAttribute(gemm_kernel<0>,
            cudaFuncAttributeMaxDynamicSharedMemorySize, GEMM_SMEM_BYTES);
        cudaFuncSetAttribute(gemm_kernel<1>,
            cudaFuncAttributeMaxDynamicSharedMemorySize, GEMM_SMEM_BYTES);
        attr_set = true;
    }

    cudaMemcpyAsync(px, in_x, sizeof(float) * (size_t)BS * E,
                    cudaMemcpyDeviceToDevice);

    {
        size_t nu = (size_t)NB * E * 2 * INNER;
        split_kernel<<<(unsigned)(nu / 4 / 256), 256>>>(w_up, puh, pul, nu);
        size_t nd = (size_t)NB * INNER * E;
        split_kernel<<<(unsigned)(nd / 4 / 256), 256>>>(w_down, pdh, pdl, nd);
    }

    for (int bi = 0; bi < NB; bi++) {
        ln_kernel<1><<<BS, 256>>>(px, E, ln_w + (size_t)bi * E,
                                  nullptr, pxh, pxl, E);

        dim3 gu(2 * INNER / 128, BS / 128);
        gemm_kernel<0><<<gu, 256, GEMM_SMEM_BYTES>>>(pxh, pxl,
                                    puh + (size_t)bi * E * 2 * INNER,
                                    pul + (size_t)bi * E * 2 * INNER,
                                    pup, BS, 2 * INNER, E);

        conv_silu_kernel<<<dim3(INNER / 256, B), 256>>>(
            conv_w + (size_t)bi * INNER * CK, conv_b + (size_t)bi * INNER);

        headwise_kernel<<<dim3(NHQ / 128, BS / 16), 128>>>(
            wq + (size_t)bi * NHQ * 16, wk + (size_t)bi * NHQ * 16,
            wv + (size_t)bi * NHQ * 16);

        gate_kernel<<<BS, 256>>>(
            ig_w + (size_t)bi * 3 * INNER * NH, ig_b + (size_t)bi * NH,
            fg_w + (size_t)bi * 3 * INNER * NH, fg_b + (size_t)bi * NH);

        cumsum_kernel<<<1, 256>>>();

        mlstm_kernel<<<dim3(S, B * NH), 256>>>();

        mhnorm_kernel<<<dim3(BS, NH), 256>>>(
            mhn_w + (size_t)bi * INNER, skip + (size_t)bi * INNER);

        dim3 gd(E / 128, BS / 128);
        gemm_kernel<1><<<gd, 256, GEMM_SMEM_BYTES>>>(phh, phl,
                                    pdh + (size_t)bi * INNER * E,
                                    pdl + (size_t)bi * INNER * E,
                                    px, BS, E, INNER);
    }

    ln_kernel<0><<<B, 256>>>(px + (size_t)(S - 1) * E, (size_t)S * E,
                             post_ln_w, plast, nullptr, nullptr, E);
    proj_kernel<<<dim3(OUT / 256, B), 256>>>(proj_w, proj_b, out);
}

// round 6
// speedup vs baseline: 1.2253x; 1.0956x over previous
#include <cuda_runtime.h>
#include <cuda_bf16.h>
#include <math.h>
#include <stdint.h>

#define E      1024
#define INNER  2048
#define NHQ    512
#define NH     4
#define DH     512
#define CK     4
#define S      46
#define B      64
#define OUT    512
#define NB     8
#define BS     (B*S)
#define TG     4

// ---------------- static scratch (no allocations allowed) ----------------
__device__ float d_x[BS * E];
__device__ float d_up[BS * 2 * INNER];
__device__ float d_xact[BS * INNER];
__device__ float d_gatein[BS * 3 * INNER];
__device__ float d_ipre[B * NH * S];
__device__ float d_fpre[B * NH * S];
__device__ float d_cum[B * NH * S];
__device__ float d_h[BS * INNER];
__device__ float d_last[B * E];

__device__ __nv_bfloat16 d_xlnhi[BS * E];
__device__ __nv_bfloat16 d_xlnlo[BS * E];
__device__ __nv_bfloat16 d_hhi[BS * INNER];
__device__ __nv_bfloat16 d_hlo[BS * INNER];
__device__ __nv_bfloat16 d_wuphi[NB * E * 2 * INNER];
__device__ __nv_bfloat16 d_wuplo[NB * E * 2 * INNER];
__device__ __nv_bfloat16 d_wdnhi[NB * INNER * E];
__device__ __nv_bfloat16 d_wdnlo[NB * INNER * E];

// ---------------- helpers ----------------
__device__ __forceinline__ uint32_t smem_u32(const void* p) {
    return (uint32_t)__cvta_generic_to_shared(p);
}
__device__ __forceinline__ void ldsm4(uint32_t& r0, uint32_t& r1, uint32_t& r2, uint32_t& r3, uint32_t addr) {
    asm volatile("ldmatrix.sync.aligned.m8n8.x4.shared.b16 {%0,%1,%2,%3}, [%4];"
                 : "=r"(r0), "=r"(r1), "=r"(r2), "=r"(r3) : "r"(addr));
}
__device__ __forceinline__ void ldsm4t(uint32_t& r0, uint32_t& r1, uint32_t& r2, uint32_t& r3, uint32_t addr) {
    asm volatile("ldmatrix.sync.aligned.m8n8.x4.trans.shared.b16 {%0,%1,%2,%3}, [%4];"
                 : "=r"(r0), "=r"(r1), "=r"(r2), "=r"(r3) : "r"(addr));
}
__device__ __forceinline__ void mma16816(float* d, const uint32_t* a, const uint32_t* b) {
    asm volatile("mma.sync.aligned.m16n8k16.row.col.f32.bf16.bf16.f32 "
                 "{%0,%1,%2,%3}, {%4,%5,%6,%7}, {%8,%9}, {%0,%1,%2,%3};"
                 : "+f"(d[0]), "+f"(d[1]), "+f"(d[2]), "+f"(d[3])
                 : "r"(a[0]), "r"(a[1]), "r"(a[2]), "r"(a[3]), "r"(b[0]), "r"(b[1]));
}
__device__ __forceinline__ void cpa16(void* sdst, const void* gsrc) {
    asm volatile("cp.async.cg.shared.global [%0], [%1], 16;"
                 :: "r"(smem_u32(sdst)), "l"(gsrc));
}
__device__ __forceinline__ void split1(float x, __nv_bfloat16& h, __nv_bfloat16& l) {
    h = __float2bfloat16_rn(x);
    l = __float2bfloat16_rn(x - __bfloat162float(h));
}

// ---------------- fp32 -> (hi,lo) bf16 split ----------------
__global__ __launch_bounds__(256) void split_kernel(
    const float* __restrict__ src, __nv_bfloat16* __restrict__ hi,
    __nv_bfloat16* __restrict__ lo, size_t n)
{
    size_t i = ((size_t)blockIdx.x * 256 + threadIdx.x) * 4;
    if (i >= n) return;
    float4 v = *(const float4*)(src + i);
    __nv_bfloat16 h0, h1, h2, h3, l0, l1, l2, l3;
    split1(v.x, h0, l0); split1(v.y, h1, l1);
    split1(v.z, h2, l2); split1(v.w, h3, l3);
    *(__nv_bfloat162*)(hi + i)     = __nv_bfloat162(h0, h1);
    *(__nv_bfloat162*)(hi + i + 2) = __nv_bfloat162(h2, h3);
    *(__nv_bfloat162*)(lo + i)     = __nv_bfloat162(l0, l1);
    *(__nv_bfloat162*)(lo + i + 2) = __nv_bfloat162(l2, l3);
}

// ---------------- LayerNorm ----------------
template<int SPLIT>
__global__ __launch_bounds__(256) void ln_kernel(
    const float* __restrict__ in, size_t in_stride,
    const float* __restrict__ w,
    float* __restrict__ outf,
    __nv_bfloat16* __restrict__ oh, __nv_bfloat16* __restrict__ ol,
    size_t out_stride)
{
    int row = blockIdx.x;
    const float* x = in + (size_t)row * in_stride;
    int tid = threadIdx.x;
    float s = 0.f, ss = 0.f;
    for (int i = tid; i < E; i += 256) { float v = x[i]; s += v; ss += v * v; }
    __shared__ float r1[256], r2[256];
    r1[tid] = s; r2[tid] = ss;
    __syncthreads();
    for (int st = 128; st > 0; st >>= 1) {
        if (tid < st) { r1[tid] += r1[tid + st]; r2[tid] += r2[tid + st]; }
        __syncthreads();
    }
    float mean = r1[0] * (1.f / E);
    float var  = r2[0] * (1.f / E) - mean * mean;
    float inv  = rsqrtf(var + 1e-5f);
    for (int i = tid; i < E; i += 256) {
        float v = (x[i] - mean) * inv * w[i];
        if (SPLIT) {
            __nv_bfloat16 h, l;
            split1(v, h, l);
            oh[(size_t)row * out_stride + i] = h;
            ol[(size_t)row * out_stride + i] = l;
        } else {
            outf[(size_t)row * out_stride + i] = v;
        }
    }
}

// ---------------- split-bf16 GEMM, cp.async 2-stage pipeline ----------------
#define A_STAGE 5120
#define B_STAGE 4352
#define GEMM_SMEM_BYTES ((2*A_STAGE*2 + 2*B_STAGE*2) * 2)

template<int ADD>
__global__ __launch_bounds__(256, 2) void gemm_kernel(
    const __nv_bfloat16* __restrict__ Ahg, const __nv_bfloat16* __restrict__ Alg,
    const __nv_bfloat16* __restrict__ Bhg, const __nv_bfloat16* __restrict__ Blg,
    float* __restrict__ C, int M, int N, int Kd)
{
    extern __shared__ __nv_bfloat16 smem[];
    __nv_bfloat16* ah = smem;
    __nv_bfloat16* al = ah + 2 * A_STAGE;
    __nv_bfloat16* bh = al + 2 * A_STAGE;
    __nv_bfloat16* bl = bh + 2 * B_STAGE;

    int tid  = threadIdx.x;
    int lane = tid & 31, warp = tid >> 5;
    int bm = blockIdx.y * 128, bn = blockIdx.x * 128;
    int wm = (warp >> 1) * 32;
    int wn = (warp & 1) * 64;

    int ar0 = tid >> 2,          ac0 = (tid & 3) * 8;
    int ar1 = (tid + 256) >> 2,  ac1 = (tid & 3) * 8;
    int br0 = tid >> 4,          bc0 = (tid & 15) * 8;
    int br1 = (tid + 256) >> 4,  bc1 = (tid & 15) * 8;

    size_t aoff0 = (size_t)(bm + ar0) * Kd + ac0;
    size_t aoff1 = (size_t)(bm + ar1) * Kd + ac1;
    size_t boff0 = (size_t)br0 * N + bn + bc0;
    size_t boff1 = (size_t)br1 * N + bn + bc1;

    int a_row = lane & 15, a_col = (lane >> 4) * 8;
    int b_row = (lane & 7) + ((lane >> 3) & 1) * 8;
    int b_col = (lane >> 4) * 8;

    float acc[2][8][4];
    #pragma unroll
    for (int i = 0; i < 2; i++)
        #pragma unroll
        for (int j = 0; j < 8; j++)
            #pragma unroll
            for (int q = 0; q < 4; q++) acc[i][j][q] = 0.f;

    int ntiles = Kd >> 5;

    auto issue = [&](int st, int kt) {
        int k0 = kt * 32;
        __nv_bfloat16* A0 = ah + st * A_STAGE;
        __nv_bfloat16* A1 = al + st * A_STAGE;
        __nv_bfloat16* B0 = bh + st * B_STAGE;
        __nv_bfloat16* B1 = bl + st * B_STAGE;
        cpa16(A0 + ar0 * 40 + ac0, Ahg + aoff0 + k0);
        cpa16(A0 + ar1 * 40 + ac1, Ahg + aoff1 + k0);
        cpa16(A1 + ar0 * 40 + ac0, Alg + aoff0 + k0);
        cpa16(A1 + ar1 * 40 + ac1, Alg + aoff1 + k0);
        cpa16(B0 + br0 * 136 + bc0, Bhg + boff0 + (size_t)k0 * N);
        cpa16(B0 + br1 * 136 + bc1, Bhg + boff1 + (size_t)k0 * N);
        cpa16(B1 + br0 * 136 + bc0, Blg + boff0 + (size_t)k0 * N);
        cpa16(B1 + br1 * 136 + bc1, Blg + boff1 + (size_t)k0 * N);
        asm volatile("cp.async.commit_group;");
    };

    issue(0, 0);

    for (int kt = 0; kt < ntiles; kt++) {
        int st = kt & 1;
        if (kt + 1 < ntiles) {
            issue(st ^ 1, kt + 1);
            asm volatile("cp.async.wait_group 1;");
        } else {
            asm volatile("cp.async.wait_group 0;");
        }
        __syncthreads();

        __nv_bfloat16* A0 = ah + st * A_STAGE;
        __nv_bfloat16* A1 = al + st * A_STAGE;
        __nv_bfloat16* B0 = bh + st * B_STAGE;
        __nv_bfloat16* B1 = bl + st * B_STAGE;

        #pragma unroll
        for (int h = 0; h < 2; h++) {
            uint32_t rah[2][4], ral[2][4];
            #pragma unroll
            for (int mt = 0; mt < 2; mt++) {
                ldsm4(rah[mt][0], rah[mt][1], rah[mt][2], rah[mt][3],
                      smem_u32(A0 + (wm + mt * 16 + a_row) * 40 + h * 16 + a_col));
                ldsm4(ral[mt][0], ral[mt][1], ral[mt][2], ral[mt][3],
                      smem_u32(A1 + (wm + mt * 16 + a_row) * 40 + h * 16 + a_col));
            }
            #pragma unroll
            for (int ng = 0; ng < 4; ng++) {
                uint32_t rbh[4], rbl[4];
                ldsm4t(rbh[0], rbh[1], rbh[2], rbh[3],
                       smem_u32(B0 + (h * 16 + b_row) * 136 + wn + ng * 16 + b_col));
                ldsm4t(rbl[0], rbl[1], rbl[2], rbl[3],
                       smem_u32(B1 + (h * 16 + b_row) * 136 + wn + ng * 16 + b_col));
                #pragma unroll
                for (int mt = 0; mt < 2; mt++) {
                    #pragma unroll
                    for (int nn = 0; nn < 2; nn++) {
                        float* d = acc[mt][ng * 2 + nn];
                        mma16816(d, rah[mt], &rbh[nn * 2]);
                        mma16816(d, rah[mt], &rbl[nn * 2]);
                        mma16816(d, ral[mt], &rbh[nn * 2]);
                    }
                }
            }
        }
        __syncthreads();
    }

    int g = lane >> 2, t2 = (lane & 3) * 2;
    #pragma unroll
    for (int mt = 0; mt < 2; mt++) {
        #pragma unroll
        for (int nt = 0; nt < 8; nt++) {
            int row = bm + wm + mt * 16 + g;
            int col = bn + wn + nt * 8 + t2;
            float* d = acc[mt][nt];
            float2* p0 = (float2*)&C[(size_t)row * N + col];
            float2* p1 = (float2*)&C[(size_t)(row + 8) * N + col];
            float2 v0 = make_float2(d[0], d[1]);
            float2 v1 = make_float2(d[2], d[3]);
            if (ADD) {
                float2 o0 = *p0, o1 = *p1;
                v0.x += o0.x; v0.y += o0.y;
                v1.x += o1.x; v1.y += o1.y;
            }
            *p0 = v0; *p1 = v1;
        }
    }
}

// ---------------- causal depthwise conv (K=4) + SiLU ----------------
__global__ __launch_bounds__(256) void conv_silu_kernel(
    const float* __restrict__ cw, const float* __restrict__ cb)
{
    int c = blockIdx.x * 256 + threadIdx.x;
    int b = blockIdx.y;
    float w0 = cw[c * CK + 0], w1 = cw[c * CK + 1];
    float w2 = cw[c * CK + 2], w3 = cw[c * CK + 3];
    float bias = cb[c];
    const float* src = d_up + (size_t)b * S * 2 * INNER + c;
    float* dst = d_xact + (size_t)b * S * INNER + c;
    float x0 = 0.f, x1 = 0.f, x2 = 0.f;
    for (int s = 0; s < S; s++) {
        float x3 = src[(size_t)s * 2 * INNER];
        float o = w0 * x0 + w1 * x1 + w2 * x2 + w3 * x3 + bias;
        dst[(size_t)s * INNER] = o / (1.f + expf(-o));
        x0 = x1; x1 = x2; x2 = x3;
    }
}

// ---------------- headwise 4x4 q/k/v ----------------
__global__ __launch_bounds__(128) void headwise_kernel(
    const float* __restrict__ wq, const float* __restrict__ wk,
    const float* __restrict__ wv)
{
    int hq = blockIdx.x * 128 + threadIdx.x;
    int r0 = blockIdx.y * 16;
    float Wq[16], Wk[16], Wv[16];
    #pragma unroll
    for (int i = 0; i < 4; i++) {
        ((float4*)Wq)[i] = ((const float4*)(wq + hq * 16))[i];
        ((float4*)Wk)[i] = ((const float4*)(wk + hq * 16))[i];
        ((float4*)Wv)[i] = ((const float4*)(wv + hq * 16))[i];
    }
    #pragma unroll 4
    for (int r = 0; r < 16; r++) {
        int row = r0 + r;
        float a[4], xi[4];
        *(float4*)a  = *(const float4*)(d_xact + (size_t)row * INNER + hq * 4);
        *(float4*)xi = *(const float4*)(d_up + (size_t)row * 2 * INNER + hq * 4);
        float qo[4], ko[4], vo[4];
        #pragma unroll
        for (int o = 0; o < 4; o++) {
            float sq = 0.f, sk = 0.f, sv = 0.f;
            #pragma unroll
            for (int d = 0; d < 4; d++) {
                sq += Wq[o * 4 + d] * a[d];
                sk += Wk[o * 4 + d] * a[d];
                sv += Wv[o * 4 + d] * xi[d];
            }
            qo[o] = sq; ko[o] = sk; vo[o] = sv;
        }
        float* gp = d_gatein + (size_t)row * 3 * INNER;
        *(float4*)(gp + hq * 4)             = *(float4*)qo;
        *(float4*)(gp + INNER + hq * 4)     = *(float4*)ko;
        *(float4*)(gp + 2 * INNER + hq * 4) = *(float4*)vo;
    }
}

// ---------------- gate pre-activations: 8 rows/block, smem-staged weights ----------------
__global__ __launch_bounds__(256) void gate_kernel(
    const float* __restrict__ igw, const float* __restrict__ igb,
    const float* __restrict__ fgw, const float* __restrict__ fgb)
{
    __shared__ float sw[1024][9];   // pad 9 -> conflict-free strided reads
    int tid = threadIdx.x, warp = tid >> 5, lane = tid & 31;
    int row = blockIdx.x * 8 + warp;
    int b = row / S, s = row - b * S;
    const float* g = d_gatein + (size_t)row * 3 * INNER;
    float acc[8] = {0.f,0.f,0.f,0.f,0.f,0.f,0.f,0.f};

    for (int k0 = 0; k0 < 3 * INNER; k0 += 1024) {
        if (k0) __syncthreads();
        for (int i = tid; i < 1024; i += 256) {
            float4 a = *(const float4*)(igw + (size_t)(k0 + i) * NH);
            float4 f = *(const float4*)(fgw + (size_t)(k0 + i) * NH);
            sw[i][0] = a.x; sw[i][1] = a.y; sw[i][2] = a.z; sw[i][3] = a.w;
            sw[i][4] = f.x; sw[i][5] = f.y; sw[i][6] = f.z; sw[i][7] = f.w;
        }
        __syncthreads();
        #pragma unroll 4
        for (int kk = lane; kk < 1024; kk += 32) {
            float gv = g[k0 + kk];
            #pragma unroll
            for (int j = 0; j < 8; j++) acc[j] += gv * sw[kk][j];
        }
    }
    #pragma unroll
    for (int off = 16; off; off >>= 1)
        #pragma unroll
        for (int j = 0; j < 8; j++)
            acc[j] += __shfl_down_sync(0xffffffffu, acc[j], off);
    if (lane == 0) {
        #pragma unroll
        for (int j = 0; j < 4; j++) {
            d_ipre[(b * NH + j) * S + s] = acc[j] + igb[j];
            d_fpre[(b * NH + j) * S + s] = acc[j + 4] + fgb[j];
        }
    }
}

// ---------------- cumsum of log-sigmoid(fpre) ----------------
__global__ void cumsum_kernel()
{
    int i = blockIdx.x * blockDim.x + threadIdx.x;
    if (i >= B * NH) return;
    const float* f = d_fpre + (size_t)i * S;
    float* c = d_cum + (size_t)i * S;
    float acc = 0.f;
    for (int s = 0; s < S; s++) {
        float x = f[s];
        float ls = (x < 0.f) ? (x - log1pf(expf(x))) : (-log1pf(expf(-x)));
        acc += ls;
        c[s] = acc;
    }
}

// ---------------- mLSTM: block per (b, h, t-group of 4); k/v shared across group ----------------
__global__ __launch_bounds__(256) void mlstm_kernel()
{
    int tg = blockIdx.x;                 // 0..11
    int bh = blockIdx.y;                 // 0..255
    int b = bh >> 2, hh = bh & 3;
    int t0 = tg * TG;
    int nt = (t0 + TG <= S) ? TG : (S - t0);
    int maxs = t0 + nt;                  // s range [0, maxs)
    int tid = threadIdx.x, warp = tid >> 5, lane = tid & 31;

    __shared__ float qs[TG][DH];
    __shared__ float cums[S], ips[S];
    __shared__ float coeff[TG][64];

    const float* gbase = d_gatein + (size_t)b * S * 3 * INNER;

    for (int i = tid; i < nt * DH; i += 256) {
        int tt = i >> 9, j = i & (DH - 1);
        qs[tt][j] = gbase[(size_t)(t0 + tt) * 3 * INNER + hh * DH + j];
    }
    if (tid < S) { cums[tid] = d_cum[bh * S + tid]; ips[tid] = d_ipre[bh * S + tid]; }
    __syncthreads();

    // phase 1: raw dots q[t0..t0+nt) · k[s], k row read once per block
    for (int s = warp; s < maxs; s += 8) {
        const float* krow = gbase + (size_t)s * 3 * INNER + INNER + hh * DH;
        float kv[16];
        #pragma unroll
        for (int j = 0; j < 16; j++) kv[j] = krow[lane + j * 32];
        #pragma unroll
        for (int tt = 0; tt < TG; tt++) {
            float p = 0.f;
            #pragma unroll
            for (int j = 0; j < 16; j++) p += qs[tt][lane + j * 32] * kv[j];
            #pragma unroll
            for (int off = 16; off; off >>= 1)
                p += __shfl_down_sync(0xffffffffu, p, off);
            if (lane == 0) coeff[tt][s] = p;
        }
    }
    __syncthreads();

    // phase 2: stabilized normalization; warp tt handles t = t0 + tt
    if (warp < nt) {
        int t = t0 + warp;
        float ct = cums[t];
        int s1 = lane, s2 = lane + 32;
        float ld1 = (s1 <= t) ? (ct - cums[s1] + ips[s1]) : -INFINITY;
        float ld2 = (s2 <= t) ? (ct - cums[s2] + ips[s2]) : -INFINITY;
        float m = fmaxf(ld1, ld2);
        #pragma unroll
        for (int off = 16; off; off >>= 1)
            m = fmaxf(m, __shfl_xor_sync(0xffffffffu, m, off));
        const float scale = 0.04419417382f;   // 512^-0.5
        float cv1 = (s1 <= t) ? coeff[warp][s1] * scale * expf(ld1 - m) : 0.f;
        float cv2 = (s2 <= t) ? coeff[warp][s2] * scale * expf(ld2 - m) : 0.f;
        float cs = cv1 + cv2;
        #pragma unroll
        for (int off = 16; off; off >>= 1)
            cs += __shfl_xor_sync(0xffffffffu, cs, off);
        float denom = fmaxf(fabsf(cs), expf(-m)) + 1e-6f;
        float inv = 1.f / denom;
        coeff[warp][s1] = cv1 * inv;
        coeff[warp][s2] = cv2 * inv;
    }
    __syncthreads();

    // phase 3: h[t] = sum_s coeff[t][s] * v[s]; v row read once per block
    int d0 = tid, d1 = tid + 256;
    float a0[TG] = {0.f, 0.f, 0.f, 0.f};
    float a1[TG] = {0.f, 0.f, 0.f, 0.f};
    for (int s = 0; s < maxs; s++) {
        const float* vrow = gbase + (size_t)s * 3 * INNER + 2 * INNER + hh * DH;
        float v0 = vrow[d0], v1 = vrow[d1];
        #pragma unroll
        for (int tt = 0; tt < TG; tt++) {
            float c = coeff[tt][s];
            a0[tt] += c * v0;
            a1[tt] += c * v1;
        }
    }
    for (int tt = 0; tt < nt; tt++) {
        float* hrow = d_h + (size_t)(b * S + t0 + tt) * INNER + hh * DH;
        hrow[d0] = a0[tt];
        hrow[d1] = a1[tt];
    }
}

// ---------------- per-head norm + skip + z-gating -> split bf16 h ----------------
__global__ __launch_bounds__(256) void mhnorm_kernel(
    const float* __restrict__ mhw, const float* __restrict__ skipw)
{
    int row = blockIdx.x;
    int hh  = blockIdx.y;
    int tid = threadIdx.x;
    const float* hp = d_h + (size_t)row * INNER + (size_t)hh * DH;
    float v0 = hp[tid], v1 = hp[tid + 256];
    __shared__ float r1[256], r2[256];
    r1[tid] = v0 + v1;
    r2[tid] = v0 * v0 + v1 * v1;
    __syncthreads();
    for (int st = 128; st > 0; st >>= 1) {
        if (tid < st) { r1[tid] += r1[tid + st]; r2[tid] += r2[tid + st]; }
        __syncthreads();
    }
    float mean = r1[0] * (1.f / DH);
    float var  = r2[0] * (1.f / DH) - mean * mean;
    float inv  = rsqrtf(var + 1e-5f);
    #pragma unroll
    for (int p = 0; p < 2; p++) {
        int i = tid + p * 256;
        int c = hh * DH + i;
        float z  = d_up[(size_t)row * 2 * INNER + INNER + c];
        float sz = z / (1.f + expf(-z));
        float hv = p ? v1 : v0;
        float val = ((hv - mean) * inv * mhw[c] + skipw[c] * d_xact[(size_t)row * INNER + c]) * sz;
        __nv_bfloat16 hi, lo;
        split1(val, hi, lo);
        d_hhi[(size_t)row * INNER + c] = hi;
        d_hlo[(size_t)row * INNER + c] = lo;
    }
}

// ---------------- final projection ----------------
__global__ void proj_kernel(const float* __restrict__ pw,
                            const float* __restrict__ pb,
                            float* __restrict__ out)
{
    int o = blockIdx.x * blockDim.x + threadIdx.x;
    int b = blockIdx.y;
    const float* l = d_last + (size_t)b * E;
    float acc = pb[o];
    for (int e = 0; e < E; e++) acc += l[e] * pw[(size_t)e * OUT + o];
    out[b * OUT + o] = acc;
}

// ---------------- host launcher ----------------
extern "C" void kernel_launch(void* const* d_in, const int* in_sizes, int n_in,
                              void* d_out, int out_size)
{
    const float* in_x      = (const float*)d_in[0];
    const float* ln_w      = (const float*)d_in[1];
    const float* w_up      = (const float*)d_in[2];
    const float* conv_w    = (const float*)d_in[3];
    const float* conv_b    = (const float*)d_in[4];
    const float* wq        = (const float*)d_in[5];
    const float* wk        = (const float*)d_in[6];
    const float* wv        = (const float*)d_in[7];
    const float* ig_w      = (const float*)d_in[8];
    const float* ig_b      = (const float*)d_in[9];
    const float* fg_w      = (const float*)d_in[10];
    const float* fg_b      = (const float*)d_in[11];
    const float* skip      = (const float*)d_in[12];
    const float* mhn_w     = (const float*)d_in[13];
    const float* w_down    = (const float*)d_in[14];
    const float* post_ln_w = (const float*)d_in[15];
    const float* proj_w    = (const float*)d_in[16];
    const float* proj_b    = (const float*)d_in[17];
    float* out = (float*)d_out;

    float *px, *pup, *plast;
    __nv_bfloat16 *pxh, *pxl, *phh, *phl, *puh, *pul, *pdh, *pdl;
    cudaGetSymbolAddress((void**)&px,    d_x);
    cudaGetSymbolAddress((void**)&pup,   d_up);
    cudaGetSymbolAddress((void**)&plast, d_last);
    cudaGetSymbolAddress((void**)&pxh,   d_xlnhi);
    cudaGetSymbolAddress((void**)&pxl,   d_xlnlo);
    cudaGetSymbolAddress((void**)&phh,   d_hhi);
    cudaGetSymbolAddress((void**)&phl,   d_hlo);
    cudaGetSymbolAddress((void**)&puh,   d_wuphi);
    cudaGetSymbolAddress((void**)&pul,   d_wuplo);
    cudaGetSymbolAddress((void**)&pdh,   d_wdnhi);
    cudaGetSymbolAddress((void**)&pdl,   d_wdnlo);

    static bool attr_set = false;
    if (!attr_set) {
        cudaFuncSetAttribute(gemm_kernel<0>,
            cudaFuncAttributeMaxDynamicSharedMemorySize, GEMM_SMEM_BYTES);
        cudaFuncSetAttribute(gemm_kernel<1>,
            cudaFuncAttributeMaxDynamicSharedMemorySize, GEMM_SMEM_BYTES);
        attr_set = true;
    }

    cudaMemcpyAsync(px, in_x, sizeof(float) * (size_t)BS * E,
                    cudaMemcpyDeviceToDevice);

    {
        size_t nu = (size_t)NB * E * 2 * INNER;
        split_kernel<<<(unsigned)(nu / 4 / 256), 256>>>(w_up, puh, pul, nu);
        size_t nd = (size_t)NB * INNER * E;
        split_kernel<<<(unsigned)(nd / 4 / 256), 256>>>(w_down, pdh, pdl, nd);
    }

    for (int bi = 0; bi < NB; bi++) {
        ln_kernel<1><<<BS, 256>>>(px, E, ln_w + (size_t)bi * E,
                                  nullptr, pxh, pxl, E);

        dim3 gu(2 * INNER / 128, BS / 128);
        gemm_kernel<0><<<gu, 256, GEMM_SMEM_BYTES>>>(pxh, pxl,
                                    puh + (size_t)bi * E * 2 * INNER,
                                    pul + (size_t)bi * E * 2 * INNER,
                                    pup, BS, 2 * INNER, E);

        conv_silu_kernel<<<dim3(INNER / 256, B), 256>>>(
            conv_w + (size_t)bi * INNER * CK, conv_b + (size_t)bi * INNER);

        headwise_kernel<<<dim3(NHQ / 128, BS / 16), 128>>>(
            wq + (size_t)bi * NHQ * 16, wk + (size_t)bi * NHQ * 16,
            wv + (size_t)bi * NHQ * 16);

        gate_kernel<<<BS / 8, 256>>>(
            ig_w + (size_t)bi * 3 * INNER * NH, ig_b + (size_t)bi * NH,
            fg_w + (size_t)bi * 3 * INNER * NH, fg_b + (size_t)bi * NH);

        cumsum_kernel<<<1, 256>>>();

        mlstm_kernel<<<dim3((S + TG - 1) / TG, B * NH), 256>>>();

        mhnorm_kernel<<<dim3(BS, NH), 256>>>(
            mhn_w + (size_t)bi * INNER, skip + (size_t)bi * INNER);

        dim3 gd(E / 128, BS / 128);
        gemm_kernel<1><<<gd, 256, GEMM_SMEM_BYTES>>>(phh, phl,
                                    pdh + (size_t)bi * INNER * E,
                                    pdl + (size_t)bi * INNER * E,
                                    px, BS, E, INNER);
    }

    ln_kernel<0><<<B, 256>>>(px + (size_t)(S - 1) * E, (size_t)S * E,
                             post_ln_w, plast, nullptr, nullptr, E);
    proj_kernel<<<dim3(OUT / 256, B), 256>>>(proj_w, proj_b, out);
}

// round 7
// speedup vs baseline: 1.3627x; 1.1122x over previous
#include <cuda_runtime.h>
#include <cuda_bf16.h>
#include <math.h>
#include <stdint.h>

#define E      1024
#define INNER  2048
#define NHQ    512
#define NH     4
#define DH     512
#define CK     4
#define S      46
#define B      64
#define OUT    512
#define NB     8
#define BS     (B*S)
#define TG     8

// ---------------- static scratch (no allocations allowed) ----------------
__device__ float d_x[BS * E];
__device__ float d_up[BS * 2 * INNER];
__device__ float d_xact[BS * INNER];
__device__ float d_gatein[BS * 3 * INNER];
__device__ float d_ipre[B * NH * S];
__device__ float d_fpre[B * NH * S];
__device__ float d_h[BS * INNER];
__device__ float d_last[B * E];

__device__ __nv_bfloat16 d_xlnhi[BS * E];
__device__ __nv_bfloat16 d_xlnlo[BS * E];
__device__ __nv_bfloat16 d_hhi[BS * INNER];
__device__ __nv_bfloat16 d_hlo[BS * INNER];
__device__ __nv_bfloat16 d_wuphi[NB * E * 2 * INNER];
__device__ __nv_bfloat16 d_wuplo[NB * E * 2 * INNER];
__device__ __nv_bfloat16 d_wdnhi[NB * INNER * E];
__device__ __nv_bfloat16 d_wdnlo[NB * INNER * E];

// ---------------- helpers ----------------
__device__ __forceinline__ uint32_t smem_u32(const void* p) {
    return (uint32_t)__cvta_generic_to_shared(p);
}
__device__ __forceinline__ void ldsm4(uint32_t& r0, uint32_t& r1, uint32_t& r2, uint32_t& r3, uint32_t addr) {
    asm volatile("ldmatrix.sync.aligned.m8n8.x4.shared.b16 {%0,%1,%2,%3}, [%4];"
                 : "=r"(r0), "=r"(r1), "=r"(r2), "=r"(r3) : "r"(addr));
}
__device__ __forceinline__ void ldsm4t(uint32_t& r0, uint32_t& r1, uint32_t& r2, uint32_t& r3, uint32_t addr) {
    asm volatile("ldmatrix.sync.aligned.m8n8.x4.trans.shared.b16 {%0,%1,%2,%3}, [%4];"
                 : "=r"(r0), "=r"(r1), "=r"(r2), "=r"(r3) : "r"(addr));
}
__device__ __forceinline__ void mma16816(float* d, const uint32_t* a, const uint32_t* b) {
    asm volatile("mma.sync.aligned.m16n8k16.row.col.f32.bf16.bf16.f32 "
                 "{%0,%1,%2,%3}, {%4,%5,%6,%7}, {%8,%9}, {%0,%1,%2,%3};"
                 : "+f"(d[0]), "+f"(d[1]), "+f"(d[2]), "+f"(d[3])
                 : "r"(a[0]), "r"(a[1]), "r"(a[2]), "r"(a[3]), "r"(b[0]), "r"(b[1]));
}
__device__ __forceinline__ void cpa16(uint32_t sdst, const void* gsrc) {
    asm volatile("cp.async.cg.shared.global [%0], [%1], 16;"
                 :: "r"(sdst), "l"(gsrc));
}
__device__ __forceinline__ void split1(float x, __nv_bfloat16& h, __nv_bfloat16& l) {
    h = __float2bfloat16_rn(x);
    l = __float2bfloat16_rn(x - __bfloat162float(h));
}

// ---------------- fp32 -> (hi,lo) bf16 split ----------------
__global__ __launch_bounds__(256) void split_kernel(
    const float* __restrict__ src, __nv_bfloat16* __restrict__ hi,
    __nv_bfloat16* __restrict__ lo, size_t n)
{
    size_t i = ((size_t)blockIdx.x * 256 + threadIdx.x) * 4;
    if (i >= n) return;
    float4 v = *(const float4*)(src + i);
    __nv_bfloat16 h0, h1, h2, h3, l0, l1, l2, l3;
    split1(v.x, h0, l0); split1(v.y, h1, l1);
    split1(v.z, h2, l2); split1(v.w, h3, l3);
    *(__nv_bfloat162*)(hi + i)     = __nv_bfloat162(h0, h1);
    *(__nv_bfloat162*)(hi + i + 2) = __nv_bfloat162(h2, h3);
    *(__nv_bfloat162*)(lo + i)     = __nv_bfloat162(l0, l1);
    *(__nv_bfloat162*)(lo + i + 2) = __nv_bfloat162(l2, l3);
}

// ---------------- LayerNorm ----------------
template<int SPLIT>
__global__ __launch_bounds__(256) void ln_kernel(
    const float* __restrict__ in, size_t in_stride,
    const float* __restrict__ w,
    float* __restrict__ outf,
    __nv_bfloat16* __restrict__ oh, __nv_bfloat16* __restrict__ ol,
    size_t out_stride)
{
    int row = blockIdx.x;
    const float* x = in + (size_t)row * in_stride;
    int tid = threadIdx.x;
    float s = 0.f, ss = 0.f;
    for (int i = tid; i < E; i += 256) { float v = x[i]; s += v; ss += v * v; }
    __shared__ float r1[256], r2[256];
    r1[tid] = s; r2[tid] = ss;
    __syncthreads();
    for (int st = 128; st > 0; st >>= 1) {
        if (tid < st) { r1[tid] += r1[tid + st]; r2[tid] += r2[tid + st]; }
        __syncthreads();
    }
    float mean = r1[0] * (1.f / E);
    float var  = r2[0] * (1.f / E) - mean * mean;
    float inv  = rsqrtf(var + 1e-5f);
    for (int i = tid; i < E; i += 256) {
        float v = (x[i] - mean) * inv * w[i];
        if (SPLIT) {
            __nv_bfloat16 h, l;
            split1(v, h, l);
            oh[(size_t)row * out_stride + i] = h;
            ol[(size_t)row * out_stride + i] = l;
        } else {
            outf[(size_t)row * out_stride + i] = v;
        }
    }
}

// ---------------- split-bf16 GEMM: 3-stage cp.async, swizzled smem ----------------
// smem per stage (32KB): Ah[128x32] @0, Al @8192, Bh[32x128] @16384, Bl @24576
// A swizzle: phys = row*64 + ((u ^ ((row>>1)&3))<<4), u = col/8 (0..3)
// B swizzle: phys = row*256 + ((u ^ (row&7))<<4),     u = col/8 (0..15)
#define STG_BYTES 32768u
#define GEMM_SMEM_BYTES (3 * 32768 + 1024)

template<int ADD>
__global__ __launch_bounds__(256, 2) void gemm_kernel(
    const __nv_bfloat16* __restrict__ Ahg, const __nv_bfloat16* __restrict__ Alg,
    const __nv_bfloat16* __restrict__ Bhg, const __nv_bfloat16* __restrict__ Blg,
    float* __restrict__ C, int M, int N, int Kd)
{
    extern __shared__ char smraw[];
    uint32_t sb = (smem_u32(smraw) + 1023u) & ~1023u;

    int tid  = threadIdx.x;
    int lane = tid & 31, warp = tid >> 5;
    int bm = blockIdx.y * 128, bn = blockIdx.x * 128;
    int wm = (warp >> 1) * 32;
    int wn = (warp & 1) * 64;

    // per-thread load geometry
    int a_r0 = tid >> 2,           a_u0 = tid & 3;
    int a_r1 = (tid + 256) >> 2,   a_u1 = tid & 3;
    uint32_t a_off0 = ((uint32_t)a_r0 << 6) + (((uint32_t)(a_u0 ^ ((a_r0 >> 1) & 3))) << 4);
    uint32_t a_off1 = ((uint32_t)a_r1 << 6) + (((uint32_t)(a_u1 ^ ((a_r1 >> 1) & 3))) << 4);
    int b_r0 = tid >> 4,           b_u0 = tid & 15;
    int b_r1 = (tid + 256) >> 4,   b_u1 = tid & 15;
    uint32_t b_off0 = ((uint32_t)b_r0 << 8) + (((uint32_t)(b_u0 ^ (b_r0 & 7))) << 4);
    uint32_t b_off1 = ((uint32_t)b_r1 << 8) + (((uint32_t)(b_u1 ^ (b_r1 & 7))) << 4);

    size_t ag0 = (size_t)(bm + a_r0) * Kd + a_u0 * 8;
    size_t ag1 = (size_t)(bm + a_r1) * Kd + a_u1 * 8;
    size_t bg0 = (size_t)b_r0 * N + bn + b_u0 * 8;
    size_t bg1 = (size_t)b_r1 * N + bn + b_u1 * 8;

    // ldmatrix lane geometry
    int a_row_l = lane & 15, a_hi_l = lane >> 4;          // A: +8 col group
    int b_row_l = (lane & 7) + ((lane >> 3) & 1) * 8;     // B k-row
    int b_hi_l  = lane >> 4;

    float acc[2][8][4];
    #pragma unroll
    for (int i = 0; i < 2; i++)
        #pragma unroll
        for (int j = 0; j < 8; j++)
            #pragma unroll
            for (int q = 0; q < 4; q++) acc[i][j][q] = 0.f;

    int ntiles = Kd >> 5;

    auto issue = [&](int kt) {
        uint32_t base = sb + (uint32_t)(kt % 3) * STG_BYTES;
        int k0 = kt * 32;
        cpa16(base + a_off0,           Ahg + ag0 + k0);
        cpa16(base + a_off1,           Ahg + ag1 + k0);
        cpa16(base + 8192u + a_off0,   Alg + ag0 + k0);
        cpa16(base + 8192u + a_off1,   Alg + ag1 + k0);
        cpa16(base + 16384u + b_off0,  Bhg + bg0 + (size_t)k0 * N);
        cpa16(base + 16384u + b_off1,  Bhg + bg1 + (size_t)k0 * N);
        cpa16(base + 24576u + b_off0,  Blg + bg0 + (size_t)k0 * N);
        cpa16(base + 24576u + b_off1,  Blg + bg1 + (size_t)k0 * N);
        asm volatile("cp.async.commit_group;");
    };

    issue(0);
    if (ntiles > 1) issue(1);

    for (int kt = 0; kt < ntiles; kt++) {
        if (kt + 1 < ntiles) asm volatile("cp.async.wait_group 1;");
        else                 asm volatile("cp.async.wait_group 0;");
        __syncthreads();
        if (kt + 2 < ntiles) issue(kt + 2);

        uint32_t base = sb + (uint32_t)(kt % 3) * STG_BYTES;

        #pragma unroll
        for (int h = 0; h < 2; h++) {
            uint32_t rah[2][4], ral[2][4];
            int a_u = h * 2 + a_hi_l;
            #pragma unroll
            for (int mt = 0; mt < 2; mt++) {
                int row = wm + mt * 16 + a_row_l;
                uint32_t ao = ((uint32_t)row << 6)
                            + (((uint32_t)(a_u ^ ((row >> 1) & 3))) << 4);
                ldsm4(rah[mt][0], rah[mt][1], rah[mt][2], rah[mt][3], base + ao);
                ldsm4(ral[mt][0], ral[mt][1], ral[mt][2], ral[mt][3], base + 8192u + ao);
            }
            int brow = h * 16 + b_row_l;
            uint32_t brsw = (uint32_t)(brow & 7);
            uint32_t bro = (uint32_t)brow << 8;
            #pragma unroll
            for (int ng = 0; ng < 4; ng++) {
                int b_u = (wn >> 3) + ng * 2 + b_hi_l;
                uint32_t bo = bro + (((uint32_t)b_u ^ brsw) << 4);
                uint32_t rbh[4], rbl[4];
                ldsm4t(rbh[0], rbh[1], rbh[2], rbh[3], base + 16384u + bo);
                ldsm4t(rbl[0], rbl[1], rbl[2], rbl[3], base + 24576u + bo);
                #pragma unroll
                for (int mt = 0; mt < 2; mt++) {
                    #pragma unroll
                    for (int nn = 0; nn < 2; nn++) {
                        float* d = acc[mt][ng * 2 + nn];
                        mma16816(d, rah[mt], &rbh[nn * 2]);
                        mma16816(d, rah[mt], &rbl[nn * 2]);
                        mma16816(d, ral[mt], &rbh[nn * 2]);
                    }
                }
            }
        }
    }

    int g = lane >> 2, t2 = (lane & 3) * 2;
    #pragma unroll
    for (int mt = 0; mt < 2; mt++) {
        #pragma unroll
        for (int nt = 0; nt < 8; nt++) {
            int row = bm + wm + mt * 16 + g;
            int col = bn + wn + nt * 8 + t2;
            float* d = acc[mt][nt];
            float2* p0 = (float2*)&C[(size_t)row * N + col];
            float2* p1 = (float2*)&C[(size_t)(row + 8) * N + col];
            float2 v0 = make_float2(d[0], d[1]);
            float2 v1 = make_float2(d[2], d[3]);
            if (ADD) {
                float2 o0 = *p0, o1 = *p1;
                v0.x += o0.x; v0.y += o0.y;
                v1.x += o1.x; v1.y += o1.y;
            }
            *p0 = v0; *p1 = v1;
        }
    }
}

// ---------------- causal depthwise conv (K=4) + SiLU ----------------
__global__ __launch_bounds__(256) void conv_silu_kernel(
    const float* __restrict__ cw, const float* __restrict__ cb)
{
    int c = blockIdx.x * 256 + threadIdx.x;
    int b = blockIdx.y;
    float w0 = cw[c * CK + 0], w1 = cw[c * CK + 1];
    float w2 = cw[c * CK + 2], w3 = cw[c * CK + 3];
    float bias = cb[c];
    const float* src = d_up + (size_t)b * S * 2 * INNER + c;
    float* dst = d_xact + (size_t)b * S * INNER + c;
    float x0 = 0.f, x1 = 0.f, x2 = 0.f;
    for (int s = 0; s < S; s++) {
        float x3 = src[(size_t)s * 2 * INNER];
        float o = w0 * x0 + w1 * x1 + w2 * x2 + w3 * x3 + bias;
        dst[(size_t)s * INNER] = o / (1.f + expf(-o));
        x0 = x1; x1 = x2; x2 = x3;
    }
}

// ---------------- headwise 4x4 q/k/v ----------------
__global__ __launch_bounds__(128) void headwise_kernel(
    const float* __restrict__ wq, const float* __restrict__ wk,
    const float* __restrict__ wv)
{
    int hq = blockIdx.x * 128 + threadIdx.x;
    int r0 = blockIdx.y * 16;
    float Wq[16], Wk[16], Wv[16];
    #pragma unroll
    for (int i = 0; i < 4; i++) {
        ((float4*)Wq)[i] = ((const float4*)(wq + hq * 16))[i];
        ((float4*)Wk)[i] = ((const float4*)(wk + hq * 16))[i];
        ((float4*)Wv)[i] = ((const float4*)(wv + hq * 16))[i];
    }
    #pragma unroll 4
    for (int r = 0; r < 16; r++) {
        int row = r0 + r;
        float a[4], xi[4];
        *(float4*)a  = *(const float4*)(d_xact + (size_t)row * INNER + hq * 4);
        *(float4*)xi = *(const float4*)(d_up + (size_t)row * 2 * INNER + hq * 4);
        float qo[4], ko[4], vo[4];
        #pragma unroll
        for (int o = 0; o < 4; o++) {
            float sq = 0.f, sk = 0.f, sv = 0.f;
            #pragma unroll
            for (int d = 0; d < 4; d++) {
                sq += Wq[o * 4 + d] * a[d];
                sk += Wk[o * 4 + d] * a[d];
                sv += Wv[o * 4 + d] * xi[d];
            }
            qo[o] = sq; ko[o] = sk; vo[o] = sv;
        }
        float* gp = d_gatein + (size_t)row * 3 * INNER;
        *(float4*)(gp + hq * 4)             = *(float4*)qo;
        *(float4*)(gp + INNER + hq * 4)     = *(float4*)ko;
        *(float4*)(gp + 2 * INNER + hq * 4) = *(float4*)vo;
    }
}

// ---------------- gate pre-activations: 8 rows/block, smem-staged weights ----------------
__global__ __launch_bounds__(256) void gate_kernel(
    const float* __restrict__ igw, const float* __restrict__ igb,
    const float* __restrict__ fgw, const float* __restrict__ fgb)
{
    __shared__ float sw[1024][9];
    int tid = threadIdx.x, warp = tid >> 5, lane = tid & 31;
    int row = blockIdx.x * 8 + warp;
    int b = row / S, s = row - b * S;
    const float* g = d_gatein + (size_t)row * 3 * INNER;
    float acc[8] = {0.f,0.f,0.f,0.f,0.f,0.f,0.f,0.f};

    for (int k0 = 0; k0 < 3 * INNER; k0 += 1024) {
        if (k0) __syncthreads();
        for (int i = tid; i < 1024; i += 256) {
            float4 a = *(const float4*)(igw + (size_t)(k0 + i) * NH);
            float4 f = *(const float4*)(fgw + (size_t)(k0 + i) * NH);
            sw[i][0] = a.x; sw[i][1] = a.y; sw[i][2] = a.z; sw[i][3] = a.w;
            sw[i][4] = f.x; sw[i][5] = f.y; sw[i][6] = f.z; sw[i][7] = f.w;
        }
        __syncthreads();
        #pragma unroll 4
        for (int kk = lane; kk < 1024; kk += 32) {
            float gv = g[k0 + kk];
            #pragma unroll
            for (int j = 0; j < 8; j++) acc[j] += gv * sw[kk][j];
        }
    }
    #pragma unroll
    for (int off = 16; off; off >>= 1)
        #pragma unroll
        for (int j = 0; j < 8; j++)
            acc[j] += __shfl_down_sync(0xffffffffu, acc[j], off);
    if (lane == 0) {
        #pragma unroll
        for (int j = 0; j < 4; j++) {
            d_ipre[(b * NH + j) * S + s] = acc[j] + igb[j];
            d_fpre[(b * NH + j) * S + s] = acc[j + 4] + fgb[j];
        }
    }
}

// ---------------- mLSTM: block per (b, h, t-group of 8); cumsum fused ----------------
__global__ __launch_bounds__(256) void mlstm_kernel()
{
    int tg = blockIdx.x;                 // 0..5
    int bh = blockIdx.y;                 // 0..255
    int b = bh >> 2, hh = bh & 3;
    int t0 = tg * TG;
    int nt = (t0 + TG <= S) ? TG : (S - t0);
    int maxs = t0 + nt;
    int tid = threadIdx.x, warp = tid >> 5, lane = tid & 31;

    __shared__ float qs[TG][DH];
    __shared__ float cums[S], ips[S], lsig[S];
    __shared__ float coeff[TG][64];

    const float* gbase = d_gatein + (size_t)b * S * 3 * INNER;

    for (int i = tid; i < nt * DH; i += 256) {
        int tt = i >> 9, j = i & (DH - 1);
        qs[tt][j] = gbase[(size_t)(t0 + tt) * 3 * INNER + hh * DH + j];
    }
    if (tid < S) {
        ips[tid] = d_ipre[bh * S + tid];
        float x = d_fpre[bh * S + tid];
        lsig[tid] = (x < 0.f) ? (x - log1pf(expf(x))) : (-log1pf(expf(-x)));
    }
    __syncthreads();

    // phase 1: raw dots q[t0..t0+nt) . k[s]
    for (int s = warp; s < maxs; s += 8) {
        const float* krow = gbase + (size_t)s * 3 * INNER + INNER + hh * DH;
        float kv[16];
        #pragma unroll
        for (int j = 0; j < 16; j++) kv[j] = krow[lane + j * 32];
        #pragma unroll
        for (int tt = 0; tt < TG; tt++) {
            float p = 0.f;
            #pragma unroll
            for (int j = 0; j < 16; j++) p += qs[tt][lane + j * 32] * kv[j];
            #pragma unroll
            for (int off = 16; off; off >>= 1)
                p += __shfl_down_sync(0xffffffffu, p, off);
            if (lane == 0) coeff[tt][s] = p;
        }
    }
    __syncthreads();

    // serial prefix of log-sigmoid -> cums
    if (tid == 0) {
        float a = 0.f;
        for (int s = 0; s < S; s++) { a += lsig[s]; cums[s] = a; }
    }
    __syncthreads();

    // phase 2: stabilized normalization; warp tt handles t = t0 + tt
    if (warp < nt) {
        int t = t0 + warp;
        float ct = cums[t];
        int s1 = lane, s2 = lane + 32;
        float ld1 = (s1 <= t) ? (ct - cums[s1] + ips[s1]) : -INFINITY;
        float ld2 = (s2 <= t) ? (ct - cums[s2] + ips[s2]) : -INFINITY;
        float m = fmaxf(ld1, ld2);
        #pragma unroll
        for (int off = 16; off; off >>= 1)
            m = fmaxf(m, __shfl_xor_sync(0xffffffffu, m, off));
        const float scale = 0.04419417382f;   // 512^-0.5
        float cv1 = (s1 <= t) ? coeff[warp][s1] * scale * expf(ld1 - m) : 0.f;
        float cv2 = (s2 <= t) ? coeff[warp][s2] * scale * expf(ld2 - m) : 0.f;
        float cs = cv1 + cv2;
        #pragma unroll
        for (int off = 16; off; off >>= 1)
            cs += __shfl_xor_sync(0xffffffffu, cs, off);
        float denom = fmaxf(fabsf(cs), expf(-m)) + 1e-6f;
        float inv = 1.f / denom;
        coeff[warp][s1] = cv1 * inv;
        coeff[warp][s2] = cv2 * inv;
    }
    __syncthreads();

    // phase 3: h[t] = sum_s coeff[t][s] * v[s]
    int d0 = tid, d1 = tid + 256;
    float a0[TG], a1[TG];
    #pragma unroll
    for (int tt = 0; tt < TG; tt++) { a0[tt] = 0.f; a1[tt] = 0.f; }
    for (int s = 0; s < maxs; s++) {
        const float* vrow = gbase + (size_t)s * 3 * INNER + 2 * INNER + hh * DH;
        float v0 = vrow[d0], v1 = vrow[d1];
        #pragma unroll
        for (int tt = 0; tt < TG; tt++) {
            float c = coeff[tt][s];
            a0[tt] += c * v0;
            a1[tt] += c * v1;
        }
    }
    for (int tt = 0; tt < nt; tt++) {
        float* hrow = d_h + (size_t)(b * S + t0 + tt) * INNER + hh * DH;
        hrow[d0] = a0[tt];
        hrow[d1] = a1[tt];
    }
}

// ---------------- per-head norm + skip + z-gating -> split bf16 h ----------------
__global__ __launch_bounds__(256) void mhnorm_kernel(
    const float* __restrict__ mhw, const float* __restrict__ skipw)
{
    int row = blockIdx.x;
    int hh  = blockIdx.y;
    int tid = threadIdx.x;
    const float* hp = d_h + (size_t)row * INNER + (size_t)hh * DH;
    float v0 = hp[tid], v1 = hp[tid + 256];
    __shared__ float r1[256], r2[256];
    r1[tid] = v0 + v1;
    r2[tid] = v0 * v0 + v1 * v1;
    __syncthreads();
    for (int st = 128; st > 0; st >>= 1) {
        if (tid < st) { r1[tid] += r1[tid + st]; r2[tid] += r2[tid + st]; }
        __syncthreads();
    }
    float mean = r1[0] * (1.f / DH);
    float var  = r2[0] * (1.f / DH) - mean * mean;
    float inv  = rsqrtf(var + 1e-5f);
    #pragma unroll
    for (int p = 0; p < 2; p++) {
        int i = tid + p * 256;
        int c = hh * DH + i;
        float z  = d_up[(size_t)row * 2 * INNER + INNER + c];
        float sz = z / (1.f + expf(-z));
        float hv = p ? v1 : v0;
        float val = ((hv - mean) * inv * mhw[c] + skipw[c] * d_xact[(size_t)row * INNER + c]) * sz;
        __nv_bfloat16 hi, lo;
        split1(val, hi, lo);
        d_hhi[(size_t)row * INNER + c] = hi;
        d_hlo[(size_t)row * INNER + c] = lo;
    }
}

// ---------------- final projection ----------------
__global__ void proj_kernel(const float* __restrict__ pw,
                            const float* __restrict__ pb,
                            float* __restrict__ out)
{
    int o = blockIdx.x * blockDim.x + threadIdx.x;
    int b = blockIdx.y;
    const float* l = d_last + (size_t)b * E;
    float acc = pb[o];
    for (int e = 0; e < E; e++) acc += l[e] * pw[(size_t)e * OUT + o];
    out[b * OUT + o] = acc;
}

// ---------------- host launcher ----------------
extern "C" void kernel_launch(void* const* d_in, const int* in_sizes, int n_in,
                              void* d_out, int out_size)
{
    const float* in_x      = (const float*)d_in[0];
    const float* ln_w      = (const float*)d_in[1];
    const float* w_up      = (const float*)d_in[2];
    const float* conv_w    = (const float*)d_in[3];
    const float* conv_b    = (const float*)d_in[4];
    const float* wq        = (const float*)d_in[5];
    const float* wk        = (const float*)d_in[6];
    const float* wv        = (const float*)d_in[7];
    const float* ig_w      = (const float*)d_in[8];
    const float* ig_b      = (const float*)d_in[9];
    const float* fg_w      = (const float*)d_in[10];
    const float* fg_b      = (const float*)d_in[11];
    const float* skip      = (const float*)d_in[12];
    const float* mhn_w     = (const float*)d_in[13];
    const float* w_down    = (const float*)d_in[14];
    const float* post_ln_w = (const float*)d_in[15];
    const float* proj_w    = (const float*)d_in[16];
    const float* proj_b    = (const float*)d_in[17];
    float* out = (float*)d_out;

    float *px, *pup, *plast;
    __nv_bfloat16 *pxh, *pxl, *phh, *phl, *puh, *pul, *pdh, *pdl;
    cudaGetSymbolAddress((void**)&px,    d_x);
    cudaGetSymbolAddress((void**)&pup,   d_up);
    cudaGetSymbolAddress((void**)&plast, d_last);
    cudaGetSymbolAddress((void**)&pxh,   d_xlnhi);
    cudaGetSymbolAddress((void**)&pxl,   d_xlnlo);
    cudaGetSymbolAddress((void**)&phh,   d_hhi);
    cudaGetSymbolAddress((void**)&phl,   d_hlo);
    cudaGetSymbolAddress((void**)&puh,   d_wuphi);
    cudaGetSymbolAddress((void**)&pul,   d_wuplo);
    cudaGetSymbolAddress((void**)&pdh,   d_wdnhi);
    cudaGetSymbolAddress((void**)&pdl,   d_wdnlo);

    static bool attr_set = false;
    if (!attr_set) {
        cudaFuncSetAttribute(gemm_kernel<0>,
            cudaFuncAttributeMaxDynamicSharedMemorySize, GEMM_SMEM_BYTES);
        cudaFuncSetAttribute(gemm_kernel<1>,
            cudaFuncAttributeMaxDynamicSharedMemorySize, GEMM_SMEM_BYTES);
        attr_set = true;
    }

    cudaMemcpyAsync(px, in_x, sizeof(float) * (size_t)BS * E,
                    cudaMemcpyDeviceToDevice);

    {
        size_t nu = (size_t)NB * E * 2 * INNER;
        split_kernel<<<(unsigned)(nu / 4 / 256), 256>>>(w_up, puh, pul, nu);
        size_t nd = (size_t)NB * INNER * E;
        split_kernel<<<(unsigned)(nd / 4 / 256), 256>>>(w_down, pdh, pdl, nd);
    }

    for (int bi = 0; bi < NB; bi++) {
        ln_kernel<1><<<BS, 256>>>(px, E, ln_w + (size_t)bi * E,
                                  nullptr, pxh, pxl, E);

        dim3 gu(2 * INNER / 128, BS / 128);
        gemm_kernel<0><<<gu, 256, GEMM_SMEM_BYTES>>>(pxh, pxl,
                                    puh + (size_t)bi * E * 2 * INNER,
                                    pul + (size_t)bi * E * 2 * INNER,
                                    pup, BS, 2 * INNER, E);

        conv_silu_kernel<<<dim3(INNER / 256, B), 256>>>(
            conv_w + (size_t)bi * INNER * CK, conv_b + (size_t)bi * INNER);

        headwise_kernel<<<dim3(NHQ / 128, BS / 16), 128>>>(
            wq + (size_t)bi * NHQ * 16, wk + (size_t)bi * NHQ * 16,
            wv + (size_t)bi * NHQ * 16);

        gate_kernel<<<BS / 8, 256>>>(
            ig_w + (size_t)bi * 3 * INNER * NH, ig_b + (size_t)bi * NH,
            fg_w + (size_t)bi * 3 * INNER * NH, fg_b + (size_t)bi * NH);

        mlstm_kernel<<<dim3((S + TG - 1) / TG, B * NH), 256>>>();

        mhnorm_kernel<<<dim3(BS, NH), 256>>>(
            mhn_w + (size_t)bi * INNER, skip + (size_t)bi * INNER);

        dim3 gd(E / 128, BS / 128);
        gemm_kernel<1><<<gd, 256, GEMM_SMEM_BYTES>>>(phh, phl,
                                    pdh + (size_t)bi * INNER * E,
                                    pdl + (size_t)bi * INNER * E,
                                    px, BS, E, INNER);
    }

    ln_kernel<0><<<B, 256>>>(px + (size_t)(S - 1) * E, (size_t)S * E,
                             post_ln_w, plast, nullptr, nullptr, E);
    proj_kernel<<<dim3(OUT / 256, B), 256>>>(proj_w, proj_b, out);
}

// round 8
// speedup vs baseline: 1.3720x; 1.0068x over previous
#include <cuda_runtime.h>
#include <cuda_bf16.h>
#include <math.h>
#include <stdint.h>

#define E      1024
#define INNER  2048
#define NHQ    512
#define NH     4
#define DH     512
#define CK     4
#define S      46
#define B      64
#define OUT    512
#define NB     8
#define BS     (B*S)
#define TG     16

// ---------------- static scratch (no allocations allowed) ----------------
__device__ float d_x[BS * E];
__device__ float d_up[BS * 2 * INNER];
__device__ float d_xact[BS * INNER];
__device__ float d_gatein[BS * 3 * INNER];
__device__ float d_ipre[B * NH * S];
__device__ float d_fpre[B * NH * S];
__device__ float d_h[BS * INNER];
__device__ float d_last[B * E];

__device__ __nv_bfloat16 d_xlnhi[BS * E];
__device__ __nv_bfloat16 d_xlnlo[BS * E];
__device__ __nv_bfloat16 d_hhi[BS * INNER];
__device__ __nv_bfloat16 d_hlo[BS * INNER];
__device__ __nv_bfloat16 d_wuphi[NB * E * 2 * INNER];
__device__ __nv_bfloat16 d_wuplo[NB * E * 2 * INNER];
__device__ __nv_bfloat16 d_wdnhi[NB * INNER * E];
__device__ __nv_bfloat16 d_wdnlo[NB * INNER * E];

// ---------------- helpers ----------------
__device__ __forceinline__ uint32_t smem_u32(const void* p) {
    return (uint32_t)__cvta_generic_to_shared(p);
}
__device__ __forceinline__ void ldsm4(uint32_t& r0, uint32_t& r1, uint32_t& r2, uint32_t& r3, uint32_t addr) {
    asm volatile("ldmatrix.sync.aligned.m8n8.x4.shared.b16 {%0,%1,%2,%3}, [%4];"
                 : "=r"(r0), "=r"(r1), "=r"(r2), "=r"(r3) : "r"(addr));
}
__device__ __forceinline__ void ldsm4t(uint32_t& r0, uint32_t& r1, uint32_t& r2, uint32_t& r3, uint32_t addr) {
    asm volatile("ldmatrix.sync.aligned.m8n8.x4.trans.shared.b16 {%0,%1,%2,%3}, [%4];"
                 : "=r"(r0), "=r"(r1), "=r"(r2), "=r"(r3) : "r"(addr));
}
__device__ __forceinline__ void mma16816(float* d, const uint32_t* a, const uint32_t* b) {
    asm volatile("mma.sync.aligned.m16n8k16.row.col.f32.bf16.bf16.f32 "
                 "{%0,%1,%2,%3}, {%4,%5,%6,%7}, {%8,%9}, {%0,%1,%2,%3};"
                 : "+f"(d[0]), "+f"(d[1]), "+f"(d[2]), "+f"(d[3])
                 : "r"(a[0]), "r"(a[1]), "r"(a[2]), "r"(a[3]), "r"(b[0]), "r"(b[1]));
}
__device__ __forceinline__ void cpa16(uint32_t sdst, const void* gsrc) {
    asm volatile("cp.async.cg.shared.global [%0], [%1], 16;"
                 :: "r"(sdst), "l"(gsrc));
}
__device__ __forceinline__ void split1(float x, __nv_bfloat16& h, __nv_bfloat16& l) {
    h = __float2bfloat16_rn(x);
    l = __float2bfloat16_rn(x - __bfloat162float(h));
}

// ---------------- fp32 -> (hi,lo) bf16 split ----------------
__global__ __launch_bounds__(256) void split_kernel(
    const float* __restrict__ src, __nv_bfloat16* __restrict__ hi,
    __nv_bfloat16* __restrict__ lo, size_t n)
{
    size_t i = ((size_t)blockIdx.x * 256 + threadIdx.x) * 4;
    if (i >= n) return;
    float4 v = *(const float4*)(src + i);
    __nv_bfloat16 h0, h1, h2, h3, l0, l1, l2, l3;
    split1(v.x, h0, l0); split1(v.y, h1, l1);
    split1(v.z, h2, l2); split1(v.w, h3, l3);
    *(__nv_bfloat162*)(hi + i)     = __nv_bfloat162(h0, h1);
    *(__nv_bfloat162*)(hi + i + 2) = __nv_bfloat162(h2, h3);
    *(__nv_bfloat162*)(lo + i)     = __nv_bfloat162(l0, l1);
    *(__nv_bfloat162*)(lo + i + 2) = __nv_bfloat162(l2, l3);
}

// ---------------- LayerNorm ----------------
template<int SPLIT>
__global__ __launch_bounds__(256) void ln_kernel(
    const float* __restrict__ in, size_t in_stride,
    const float* __restrict__ w,
    float* __restrict__ outf,
    __nv_bfloat16* __restrict__ oh, __nv_bfloat16* __restrict__ ol,
    size_t out_stride)
{
    int row = blockIdx.x;
    const float* x = in + (size_t)row * in_stride;
    int tid = threadIdx.x;
    float s = 0.f, ss = 0.f;
    for (int i = tid; i < E; i += 256) { float v = x[i]; s += v; ss += v * v; }
    __shared__ float r1[256], r2[256];
    r1[tid] = s; r2[tid] = ss;
    __syncthreads();
    for (int st = 128; st > 0; st >>= 1) {
        if (tid < st) { r1[tid] += r1[tid + st]; r2[tid] += r2[tid + st]; }
        __syncthreads();
    }
    float mean = r1[0] * (1.f / E);
    float var  = r2[0] * (1.f / E) - mean * mean;
    float inv  = rsqrtf(var + 1e-5f);
    for (int i = tid; i < E; i += 256) {
        float v = (x[i] - mean) * inv * w[i];
        if (SPLIT) {
            __nv_bfloat16 h, l;
            split1(v, h, l);
            oh[(size_t)row * out_stride + i] = h;
            ol[(size_t)row * out_stride + i] = l;
        } else {
            outf[(size_t)row * out_stride + i] = v;
        }
    }
}

// ---------------- split-bf16 GEMM: 3-stage cp.async, swizzled smem ----------------
// M-tile 128, N-tile NT (128 or 64). stage: Ah@0 (8KB), Al@8192, Bh@16384, Bl@16384+BTILE
// A swizzle: phys = row*64 + ((u ^ ((row>>1)&3))<<4), u = col/8 (0..3)
// B swizzle: phys = row*(NT*2) + ((u ^ (row&7))<<4),  u = col/8
template<int ADD, int NT>
__global__ __launch_bounds__(256, 2) void gemm_kernel(
    const __nv_bfloat16* __restrict__ Ahg, const __nv_bfloat16* __restrict__ Alg,
    const __nv_bfloat16* __restrict__ Bhg, const __nv_bfloat16* __restrict__ Blg,
    float* __restrict__ C, int M, int N, int Kd)
{
    constexpr int BU = NT / 8;             // 16B units per B row
    constexpr uint32_t BROWB = NT * 2;     // B row stride bytes
    constexpr uint32_t BTILE = 32u * NT * 2u;
    constexpr uint32_t STG = 16384u + 2u * BTILE;
    constexpr uint32_t OBH = 16384u, OBL = 16384u + BTILE;
    constexpr int NGRP = NT / 32;          // 16-col groups per warp
    constexpr int BCH = (NT == 128) ? 2 : 1;

    extern __shared__ char smraw[];
    uint32_t sb = (smem_u32(smraw) + 1023u) & ~1023u;

    int tid  = threadIdx.x;
    int lane = tid & 31, warp = tid >> 5;
    int bm = blockIdx.y * 128, bn = blockIdx.x * NT;
    int wm = (warp >> 1) * 32;
    int wn = (warp & 1) * (NT / 2);

    // A load geometry
    int a_r0 = tid >> 2,           a_u0 = tid & 3;
    int a_r1 = (tid + 256) >> 2,   a_u1 = tid & 3;
    uint32_t a_off0 = ((uint32_t)a_r0 << 6) + (((uint32_t)(a_u0 ^ ((a_r0 >> 1) & 3))) << 4);
    uint32_t a_off1 = ((uint32_t)a_r1 << 6) + (((uint32_t)(a_u1 ^ ((a_r1 >> 1) & 3))) << 4);
    size_t ag0 = (size_t)(bm + a_r0) * Kd + a_u0 * 8;
    size_t ag1 = (size_t)(bm + a_r1) * Kd + a_u1 * 8;

    // B load geometry
    int b_r0 = tid / BU,           b_u0 = tid % BU;
    uint32_t b_off0 = (uint32_t)b_r0 * BROWB + (((uint32_t)(b_u0 ^ (b_r0 & 7))) << 4);
    size_t bg0 = (size_t)b_r0 * N + bn + b_u0 * 8;
    int b_r1 = (tid + 256) / BU,   b_u1 = tid % BU;
    uint32_t b_off1 = (uint32_t)b_r1 * BROWB + (((uint32_t)(b_u1 ^ (b_r1 & 7))) << 4);
    size_t bg1 = (size_t)b_r1 * N + bn + b_u1 * 8;

    // ldmatrix lane geometry
    int a_row_l = lane & 15, a_hi_l = lane >> 4;
    int b_row_l = (lane & 7) + ((lane >> 3) & 1) * 8;
    int b_hi_l  = lane >> 4;

    float acc[2][2 * NGRP][4];
    #pragma unroll
    for (int i = 0; i < 2; i++)
        #pragma unroll
        for (int j = 0; j < 2 * NGRP; j++)
            #pragma unroll
            for (int q = 0; q < 4; q++) acc[i][j][q] = 0.f;

    int ntiles = Kd >> 5;

    auto issue = [&](int kt) {
        uint32_t base = sb + (uint32_t)(kt % 3) * STG;
        int k0 = kt * 32;
        cpa16(base + a_off0,         Ahg + ag0 + k0);
        cpa16(base + a_off1,         Ahg + ag1 + k0);
        cpa16(base + 8192u + a_off0, Alg + ag0 + k0);
        cpa16(base + 8192u + a_off1, Alg + ag1 + k0);
        cpa16(base + OBH + b_off0,   Bhg + bg0 + (size_t)k0 * N);
        cpa16(base + OBL + b_off0,   Blg + bg0 + (size_t)k0 * N);
        if (BCH == 2) {
            cpa16(base + OBH + b_off1, Bhg + bg1 + (size_t)k0 * N);
            cpa16(base + OBL + b_off1, Blg + bg1 + (size_t)k0 * N);
        }
        asm volatile("cp.async.commit_group;");
    };

    issue(0);
    if (ntiles > 1) issue(1);

    for (int kt = 0; kt < ntiles; kt++) {
        if (kt + 1 < ntiles) asm volatile("cp.async.wait_group 1;");
        else                 asm volatile("cp.async.wait_group 0;");
        __syncthreads();
        if (kt + 2 < ntiles) issue(kt + 2);

        uint32_t base = sb + (uint32_t)(kt % 3) * STG;

        #pragma unroll
        for (int h = 0; h < 2; h++) {
            uint32_t rah[2][4], ral[2][4];
            int a_u = h * 2 + a_hi_l;
            #pragma unroll
            for (int mt = 0; mt < 2; mt++) {
                int row = wm + mt * 16 + a_row_l;
                uint32_t ao = ((uint32_t)row << 6)
                            + (((uint32_t)(a_u ^ ((row >> 1) & 3))) << 4);
                ldsm4(rah[mt][0], rah[mt][1], rah[mt][2], rah[mt][3], base + ao);
                ldsm4(ral[mt][0], ral[mt][1], ral[mt][2], ral[mt][3], base + 8192u + ao);
            }
            int brow = h * 16 + b_row_l;
            uint32_t brsw = (uint32_t)(brow & 7);
            uint32_t bro = (uint32_t)brow * BROWB;
            #pragma unroll
            for (int ng = 0; ng < NGRP; ng++) {
                int b_u = (wn >> 3) + ng * 2 + b_hi_l;
                uint32_t bo = bro + (((uint32_t)b_u ^ brsw) << 4);
                uint32_t rbh[4], rbl[4];
                ldsm4t(rbh[0], rbh[1], rbh[2], rbh[3], base + OBH + bo);
                ldsm4t(rbl[0], rbl[1], rbl[2], rbl[3], base + OBL + bo);
                #pragma unroll
                for (int mt = 0; mt < 2; mt++) {
                    #pragma unroll
                    for (int nn = 0; nn < 2; nn++) {
                        float* d = acc[mt][ng * 2 + nn];
                        mma16816(d, rah[mt], &rbh[nn * 2]);
                        mma16816(d, rah[mt], &rbl[nn * 2]);
                        mma16816(d, ral[mt], &rbh[nn * 2]);
                    }
                }
            }
        }
    }

    int g = lane >> 2, t2 = (lane & 3) * 2;
    #pragma unroll
    for (int mt = 0; mt < 2; mt++) {
        #pragma unroll
        for (int nt = 0; nt < 2 * NGRP; nt++) {
            int row = bm + wm + mt * 16 + g;
            int col = bn + wn + nt * 8 + t2;
            float* d = acc[mt][nt];
            float2* p0 = (float2*)&C[(size_t)row * N + col];
            float2* p1 = (float2*)&C[(size_t)(row + 8) * N + col];
            float2 v0 = make_float2(d[0], d[1]);
            float2 v1 = make_float2(d[2], d[3]);
            if (ADD) {
                float2 o0 = *p0, o1 = *p1;
                v0.x += o0.x; v0.y += o0.y;
                v1.x += o1.x; v1.y += o1.y;
            }
            *p0 = v0; *p1 = v1;
        }
    }
}

#define GEMM_SMEM_UP (3 * 32768 + 1024)
#define GEMM_SMEM_DN (3 * 24576 + 1024)

// ---------------- fused causal dwconv + SiLU + headwise q/k/v ----------------
// block = (64 hq heads = 256 channels, one batch). x_in staged in smem once.
// smem: sx[4][64][53] (x_in, sp = s+3, rows 0..2 zero), sw[64][69] (weights)
#define CH_SX   (4 * 64 * 53)
#define CH_SW   (64 * 69)
#define CH_SMEM ((CH_SX + CH_SW) * 4)

__global__ __launch_bounds__(256) void conv_head_kernel(
    const float* __restrict__ cw, const float* __restrict__ cb,
    const float* __restrict__ wq, const float* __restrict__ wk,
    const float* __restrict__ wv)
{
    extern __shared__ float cs[];
    float* sx = cs;            // (j*64 + hq)*53 + sp
    float* sw = cs + CH_SX;    // hq*69 + w
    int hq0 = blockIdx.x * 64;
    int b   = blockIdx.y;
    int tid = threadIdx.x, warp = tid >> 5, lane = tid & 31;

    // zero left pad (sp = 0..2)
    for (int i = tid; i < 4 * 64 * 3; i += 256) {
        int ch2 = i / 3, sp = i - ch2 * 3;
        sx[ch2 * 53 + sp] = 0.f;
    }
    // stage x_in
    for (int i = tid; i < S * 256; i += 256) {
        int s = i >> 8, c = i & 255;
        int j = c & 3, hql = c >> 2;
        sx[(j * 64 + hql) * 53 + 3 + s] =
            d_up[((size_t)(b * S + s)) * 2 * INNER + hq0 * 4 + c];
    }
    // stage weights: per hq: cw[16] cb[4] wq[16] wk[16] wv[16] = 68
    for (int i = tid; i < 64 * 68; i += 256) {
        int hql = i / 68, w = i - hql * 68;
        int hg = hq0 + hql;
        float v;
        if (w < 16)      v = cw[hg * 16 + w];
        else if (w < 20) v = cb[hg * 4 + (w - 16)];
        else if (w < 36) v = wq[hg * 16 + (w - 20)];
        else if (w < 52) v = wk[hg * 16 + (w - 36)];
        else             v = wv[hg * 16 + (w - 52)];
        sw[hql * 69 + w] = v;
    }
    __syncthreads();

    for (int hqi = lane; hqi < 64; hqi += 32) {
        float W[68];
        #pragma unroll
        for (int w = 0; w < 68; w++) W[w] = sw[hqi * 69 + w];
        for (int s = warp; s < S; s += 8) {
            size_t row = (size_t)b * S + s;
            float a[4], xi[4];
            #pragma unroll
            for (int j = 0; j < 4; j++) {
                const float* xp = &sx[(j * 64 + hqi) * 53 + s];  // taps x[s-3..s]
                float o = W[j*4+0]*xp[0] + W[j*4+1]*xp[1]
                        + W[j*4+2]*xp[2] + W[j*4+3]*xp[3] + W[16+j];
                a[j]  = o / (1.f + expf(-o));
                xi[j] = xp[3];
            }
            *(float4*)(d_xact + row * INNER + (hq0 + hqi) * 4) = *(float4*)a;
            float qo[4], ko[4], vo[4];
            #pragma unroll
            for (int o = 0; o < 4; o++) {
                float sq = 0.f, sk = 0.f, sv = 0.f;
                #pragma unroll
                for (int d = 0; d < 4; d++) {
                    sq += W[20 + o*4 + d] * a[d];
                    sk += W[36 + o*4 + d] * a[d];
                    sv += W[52 + o*4 + d] * xi[d];
                }
                qo[o] = sq; ko[o] = sk; vo[o] = sv;
            }
            float* gp = d_gatein + row * 3 * INNER;
            *(float4*)(gp + (hq0 + hqi) * 4)             = *(float4*)qo;
            *(float4*)(gp + INNER + (hq0 + hqi) * 4)     = *(float4*)ko;
            *(float4*)(gp + 2 * INNER + (hq0 + hqi) * 4) = *(float4*)vo;
        }
    }
}

// ---------------- gate pre-activations: 8 rows/block, smem-staged weights ----------------
__global__ __launch_bounds__(256) void gate_kernel(
    const float* __restrict__ igw, const float* __restrict__ igb,
    const float* __restrict__ fgw, const float* __restrict__ fgb)
{
    __shared__ float sw[1024][9];
    int tid = threadIdx.x, warp = tid >> 5, lane = tid & 31;
    int row = blockIdx.x * 8 + warp;
    int b = row / S, s = row - b * S;
    const float* g = d_gatein + (size_t)row * 3 * INNER;
    float acc[8] = {0.f,0.f,0.f,0.f,0.f,0.f,0.f,0.f};

    for (int k0 = 0; k0 < 3 * INNER; k0 += 1024) {
        if (k0) __syncthreads();
        for (int i = tid; i < 1024; i += 256) {
            float4 a = *(const float4*)(igw + (size_t)(k0 + i) * NH);
            float4 f = *(const float4*)(fgw + (size_t)(k0 + i) * NH);
            sw[i][0] = a.x; sw[i][1] = a.y; sw[i][2] = a.z; sw[i][3] = a.w;
            sw[i][4] = f.x; sw[i][5] = f.y; sw[i][6] = f.z; sw[i][7] = f.w;
        }
        __syncthreads();
        #pragma unroll 4
        for (int kk = lane; kk < 1024; kk += 32) {
            float gv = g[k0 + kk];
            #pragma unroll
            for (int j = 0; j < 8; j++) acc[j] += gv * sw[kk][j];
        }
    }
    #pragma unroll
    for (int off = 16; off; off >>= 1)
        #pragma unroll
        for (int j = 0; j < 8; j++)
            acc[j] += __shfl_down_sync(0xffffffffu, acc[j], off);
    if (lane == 0) {
        #pragma unroll
        for (int j = 0; j < 4; j++) {
            d_ipre[(b * NH + j) * S + s] = acc[j] + igb[j];
            d_fpre[(b * NH + j) * S + s] = acc[j + 4] + fgb[j];
        }
    }
}

// ---------------- mLSTM: block per (b, h, t-group of 16); cumsum fused ----------------
__global__ __launch_bounds__(256) void mlstm_kernel()
{
    int tg = blockIdx.x;                 // 0..2
    int bh = blockIdx.y;                 // 0..255
    int b = bh >> 2, hh = bh & 3;
    int t0 = tg * TG;
    int nt = (t0 + TG <= S) ? TG : (S - t0);
    int maxs = t0 + nt;
    int tid = threadIdx.x, warp = tid >> 5, lane = tid & 31;

    __shared__ float qs[TG][DH];
    __shared__ float cums[S], ips[S], lsig[S];
    __shared__ float coeff[TG][64];

    const float* gbase = d_gatein + (size_t)b * S * 3 * INNER;

    for (int i = tid; i < nt * DH; i += 256) {
        int tt = i >> 9, j = i & (DH - 1);
        qs[tt][j] = gbase[(size_t)(t0 + tt) * 3 * INNER + hh * DH + j];
    }
    if (tid < S) {
        ips[tid] = d_ipre[bh * S + tid];
        float x = d_fpre[bh * S + tid];
        lsig[tid] = (x < 0.f) ? (x - log1pf(expf(x))) : (-log1pf(expf(-x)));
    }
    __syncthreads();

    // phase 1: raw dots q[t0..t0+nt) . k[s]
    for (int s = warp; s < maxs; s += 8) {
        const float* krow = gbase + (size_t)s * 3 * INNER + INNER + hh * DH;
        float kv[16];
        #pragma unroll
        for (int j = 0; j < 16; j++) kv[j] = krow[lane + j * 32];
        #pragma unroll
        for (int tt = 0; tt < TG; tt++) {
            float p = 0.f;
            #pragma unroll
            for (int j = 0; j < 16; j++) p += qs[tt][lane + j * 32] * kv[j];
            #pragma unroll
            for (int off = 16; off; off >>= 1)
                p += __shfl_down_sync(0xffffffffu, p, off);
            if (lane == 0) coeff[tt][s] = p;
        }
    }
    __syncthreads();

    // serial prefix of log-sigmoid -> cums
    if (tid == 0) {
        float a = 0.f;
        for (int s = 0; s < S; s++) { a += lsig[s]; cums[s] = a; }
    }
    __syncthreads();

    // phase 2: stabilized normalization; warp-strided over tt
    for (int tt = warp; tt < nt; tt += 8) {
        int t = t0 + tt;
        float ct = cums[t];
        int s1 = lane, s2 = lane + 32;
        float ld1 = (s1 <= t) ? (ct - cums[s1] + ips[s1]) : -INFINITY;
        float ld2 = (s2 <= t) ? (ct - cums[s2] + ips[s2]) : -INFINITY;
        float m = fmaxf(ld1, ld2);
        #pragma unroll
        for (int off = 16; off; off >>= 1)
            m = fmaxf(m, __shfl_xor_sync(0xffffffffu, m, off));
        const float scale = 0.04419417382f;   // 512^-0.5
        float cv1 = (s1 <= t) ? coeff[tt][s1] * scale * expf(ld1 - m) : 0.f;
        float cv2 = (s2 <= t) ? coeff[tt][s2] * scale * expf(ld2 - m) : 0.f;
        float cs = cv1 + cv2;
        #pragma unroll
        for (int off = 16; off; off >>= 1)
            cs += __shfl_xor_sync(0xffffffffu, cs, off);
        float denom = fmaxf(fabsf(cs), expf(-m)) + 1e-6f;
        float inv = 1.f / denom;
        coeff[tt][s1] = cv1 * inv;
        coeff[tt][s2] = cv2 * inv;
    }
    __syncthreads();

    // phase 3: h[t] = sum_s coeff[t][s] * v[s]
    int d0 = tid, d1 = tid + 256;
    float a0[TG], a1[TG];
    #pragma unroll
    for (int tt = 0; tt < TG; tt++) { a0[tt] = 0.f; a1[tt] = 0.f; }
    for (int s = 0; s < maxs; s++) {
        const float* vrow = gbase + (size_t)s * 3 * INNER + 2 * INNER + hh * DH;
        float v0 = vrow[d0], v1 = vrow[d1];
        #pragma unroll
        for (int tt = 0; tt < TG; tt++) {
            float c = coeff[tt][s];
            a0[tt] += c * v0;
            a1[tt] += c * v1;
        }
    }
    for (int tt = 0; tt < nt; tt++) {
        float* hrow = d_h + (size_t)(b * S + t0 + tt) * INNER + hh * DH;
        hrow[d0] = a0[tt];
        hrow[d1] = a1[tt];
    }
}

// ---------------- per-head norm + skip + z-gating -> split bf16 h ----------------
__global__ __launch_bounds__(256) void mhnorm_kernel(
    const float* __restrict__ mhw, const float* __restrict__ skipw)
{
    int row = blockIdx.x;
    int hh  = blockIdx.y;
    int tid = threadIdx.x;
    const float* hp = d_h + (size_t)row * INNER + (size_t)hh * DH;
    float v0 = hp[tid], v1 = hp[tid + 256];
    __shared__ float r1[256], r2[256];
    r1[tid] = v0 + v1;
    r2[tid] = v0 * v0 + v1 * v1;
    __syncthreads();
    for (int st = 128; st > 0; st >>= 1) {
        if (tid < st) { r1[tid] += r1[tid + st]; r2[tid] += r2[tid + st]; }
        __syncthreads();
    }
    float mean = r1[0] * (1.f / DH);
    float var  = r2[0] * (1.f / DH) - mean * mean;
    float inv  = rsqrtf(var + 1e-5f);
    #pragma unroll
    for (int p = 0; p < 2; p++) {
        int i = tid + p * 256;
        int c = hh * DH + i;
        float z  = d_up[(size_t)row * 2 * INNER + INNER + c];
        float sz = z / (1.f + expf(-z));
        float hv = p ? v1 : v0;
        float val = ((hv - mean) * inv * mhw[c] + skipw[c] * d_xact[(size_t)row * INNER + c]) * sz;
        __nv_bfloat16 hi, lo;
        split1(val, hi, lo);
        d_hhi[(size_t)row * INNER + c] = hi;
        d_hlo[(size_t)row * INNER + c] = lo;
    }
}

// ---------------- final projection ----------------
__global__ void proj_kernel(const float* __restrict__ pw,
                            const float* __restrict__ pb,
                            float* __restrict__ out)
{
    int o = blockIdx.x * blockDim.x + threadIdx.x;
    int b = blockIdx.y;
    const float* l = d_last + (size_t)b * E;
    float acc = pb[o];
    for (int e = 0; e < E; e++) acc += l[e] * pw[(size_t)e * OUT + o];
    out[b * OUT + o] = acc;
}

// ---------------- host launcher ----------------
extern "C" void kernel_launch(void* const* d_in, const int* in_sizes, int n_in,
                              void* d_out, int out_size)
{
    const float* in_x      = (const float*)d_in[0];
    const float* ln_w      = (const float*)d_in[1];
    const float* w_up      = (const float*)d_in[2];
    const float* conv_w    = (const float*)d_in[3];
    const float* conv_b    = (const float*)d_in[4];
    const float* wq        = (const float*)d_in[5];
    const float* wk        = (const float*)d_in[6];
    const float* wv        = (const float*)d_in[7];
    const float* ig_w      = (const float*)d_in[8];
    const float* ig_b      = (const float*)d_in[9];
    const float* fg_w      = (const float*)d_in[10];
    const float* fg_b      = (const float*)d_in[11];
    const float* skip      = (const float*)d_in[12];
    const float* mhn_w     = (const float*)d_in[13];
    const float* w_down    = (const float*)d_in[14];
    const float* post_ln_w = (const float*)d_in[15];
    const float* proj_w    = (const float*)d_in[16];
    const float* proj_b    = (const float*)d_in[17];
    float* out = (float*)d_out;

    float *px, *pup, *plast;
    __nv_bfloat16 *pxh, *pxl, *phh, *phl, *puh, *pul, *pdh, *pdl;
    cudaGetSymbolAddress((void**)&px,    d_x);
    cudaGetSymbolAddress((void**)&pup,   d_up);
    cudaGetSymbolAddress((void**)&plast, d_last);
    cudaGetSymbolAddress((void**)&pxh,   d_xlnhi);
    cudaGetSymbolAddress((void**)&pxl,   d_xlnlo);
    cudaGetSymbolAddress((void**)&phh,   d_hhi);
    cudaGetSymbolAddress((void**)&phl,   d_hlo);
    cudaGetSymbolAddress((void**)&puh,   d_wuphi);
    cudaGetSymbolAddress((void**)&pul,   d_wuplo);
    cudaGetSymbolAddress((void**)&pdh,   d_wdnhi);
    cudaGetSymbolAddress((void**)&pdl,   d_wdnlo);

    static bool attr_set = false;
    if (!attr_set) {
        cudaFuncSetAttribute((const void*)gemm_kernel<0, 128>,
            cudaFuncAttributeMaxDynamicSharedMemorySize, GEMM_SMEM_UP);
        cudaFuncSetAttribute((const void*)gemm_kernel<1, 64>,
            cudaFuncAttributeMaxDynamicSharedMemorySize, GEMM_SMEM_DN);
        cudaFuncSetAttribute((const void*)conv_head_kernel,
            cudaFuncAttributeMaxDynamicSharedMemorySize, CH_SMEM);
        attr_set = true;
    }

    cudaMemcpyAsync(px, in_x, sizeof(float) * (size_t)BS * E,
                    cudaMemcpyDeviceToDevice);

    {
        size_t nu = (size_t)NB * E * 2 * INNER;
        split_kernel<<<(unsigned)(nu / 4 / 256), 256>>>(w_up, puh, pul, nu);
        size_t nd = (size_t)NB * INNER * E;
        split_kernel<<<(unsigned)(nd / 4 / 256), 256>>>(w_down, pdh, pdl, nd);
    }

    for (int bi = 0; bi < NB; bi++) {
        ln_kernel<1><<<BS, 256>>>(px, E, ln_w + (size_t)bi * E,
                                  nullptr, pxh, pxl, E);

        dim3 gu(2 * INNER / 128, BS / 128);
        gemm_kernel<0, 128><<<gu, 256, GEMM_SMEM_UP>>>(pxh, pxl,
                                    puh + (size_t)bi * E * 2 * INNER,
                                    pul + (size_t)bi * E * 2 * INNER,
                                    pup, BS, 2 * INNER, E);

        conv_head_kernel<<<dim3(NHQ / 64, B), 256, CH_SMEM>>>(
            conv_w + (size_t)bi * INNER * CK, conv_b + (size_t)bi * INNER,
            wq + (size_t)bi * NHQ * 16, wk + (size_t)bi * NHQ * 16,
            wv + (size_t)bi * NHQ * 16);

        gate_kernel<<<BS / 8, 256>>>(
            ig_w + (size_t)bi * 3 * INNER * NH, ig_b + (size_t)bi * NH,
            fg_w + (size_t)bi * 3 * INNER * NH, fg_b + (size_t)bi * NH);

        mlstm_kernel<<<dim3((S + TG - 1) / TG, B * NH), 256>>>();

        mhnorm_kernel<<<dim3(BS, NH), 256>>>(
            mhn_w + (size_t)bi * INNER, skip + (size_t)bi * INNER);

        dim3 gd(E / 64, BS / 128);
        gemm_kernel<1, 64><<<gd, 256, GEMM_SMEM_DN>>>(phh, phl,
                                    pdh + (size_t)bi * INNER * E,
                                    pdl + (size_t)bi * INNER * E,
                                    px, BS, E, INNER);
    }

    ln_kernel<0><<<B, 256>>>(px + (size_t)(S - 1) * E, (size_t)S * E,
                             post_ln_w, plast, nullptr, nullptr, E);
    proj_kernel<<<dim3(OUT / 256, B), 256>>>(proj_w, proj_b, out);
}